// round 4
// baseline (speedup 1.0000x reference)
#include <cuda_runtime.h>
#include <cstdint>

// Problem constants
#define B_  4
#define S_  2048
#define D_  512
#define H_  8
#define HD_ 64
#define M_  (B_*S_)       // 8192
#define NW_ 512

// Scratch (device globals)
__device__ float g_q[M_ * NW_];
__device__ float g_k[M_ * NW_];
__device__ float g_v[M_ * NW_];
__device__ float g_ctx[M_ * NW_];

__device__ __forceinline__ unsigned f2tf(float f) {
    unsigned u;
    asm("cvt.rna.tf32.f32 %0, %1;" : "=r"(u) : "f"(f));
    return u;
}

__device__ __forceinline__ void mma_tf32(float* c, const unsigned* a, const unsigned* b) {
    asm volatile("mma.sync.aligned.m16n8k8.row.col.f32.tf32.tf32.f32 "
        "{%0,%1,%2,%3}, {%4,%5,%6,%7}, {%8,%9}, {%0,%1,%2,%3};"
        : "+f"(c[0]), "+f"(c[1]), "+f"(c[2]), "+f"(c[3])
        : "r"(a[0]), "r"(a[1]), "r"(a[2]), "r"(a[3]), "r"(b[0]), "r"(b[1]));
}

// ---------------------------------------------------------------------------
// tf32 GEMM: C[8192,512] = A[8192,512] @ W(512,512) + bias[512]
// (unchanged from round 3 — passed, ~50us each)
// ---------------------------------------------------------------------------
#define GBM 128
#define GBN 128
#define GBK 16
#define AST2 24
#define GST 136

template<bool HEADW>
__global__ __launch_bounds__(256)
void gemm_tf32_kernel(const float* __restrict__ Ain,
                      const float* __restrict__ W,
                      const float* __restrict__ bias,
                      float* __restrict__ Cout,
                      int asel, int csel)
{
    const float* A = asel ? g_ctx : Ain;
    float* C = (csel == 0) ? g_q : (csel == 1) ? g_k : (csel == 2) ? g_v : Cout;

    __shared__ __align__(16) unsigned As[GBM * AST2];
    __shared__ __align__(16) unsigned Bs[GBK * GST];

    const int tid  = threadIdx.x;
    const int lane = tid & 31;
    const int w    = tid >> 5;
    const int g    = lane >> 2;
    const int t    = lane & 3;

    const int bm0 = blockIdx.x * GBM;
    const int bn0 = blockIdx.y * GBN;
    const int wm0 = (w & 1) * 64;
    const int wn0 = (w >> 1) * 32;

    const int aRow = tid >> 1;
    const int aK   = (tid & 1) * 8;
    const int bK   = tid >> 4;
    const int bN   = (tid & 15) * 8;

    float acc[4][4][4];
#pragma unroll
    for (int mt = 0; mt < 4; mt++)
#pragma unroll
        for (int nt = 0; nt < 4; nt++)
#pragma unroll
            for (int i = 0; i < 4; i++) acc[mt][nt][i] = 0.f;

    for (int k0 = 0; k0 < 512; k0 += GBK) {
        {
            const float* ap = A + (size_t)(bm0 + aRow) * 512 + k0 + aK;
            float4 a0 = *(const float4*)ap;
            float4 a1 = *(const float4*)(ap + 4);
            uint4 u0 = make_uint4(f2tf(a0.x), f2tf(a1.x), f2tf(a0.y), f2tf(a1.y));
            uint4 u1 = make_uint4(f2tf(a0.z), f2tf(a1.z), f2tf(a0.w), f2tf(a1.w));
            *(uint4*)&As[aRow * AST2 + aK + 0] = u0;
            *(uint4*)&As[aRow * AST2 + aK + 4] = u1;
        }
#pragma unroll
        for (int j = 0; j < 2; j++) {
            int n = bn0 + bN + j * 4;
            const float* bp;
            if (HEADW) bp = W + (size_t)(n >> 6) * (D_ * 64) + (size_t)(k0 + bK) * 64 + (n & 63);
            else       bp = W + (size_t)(k0 + bK) * 512 + n;
            float4 bv = *(const float4*)bp;
            Bs[bK * GST + bN + j * 4 + 0] = f2tf(bv.x);
            Bs[bK * GST + bN + j * 4 + 1] = f2tf(bv.y);
            Bs[bK * GST + bN + j * 4 + 2] = f2tf(bv.z);
            Bs[bK * GST + bN + j * 4 + 3] = f2tf(bv.w);
        }
        __syncthreads();

#pragma unroll
        for (int kc = 0; kc < 2; kc++) {
            const int kb = kc * 8;
            unsigned af[4][4], bf[4][2];
#pragma unroll
            for (int mt = 0; mt < 4; mt++) {
                int r = wm0 + mt * 16 + g;
                uint2 lo = *(const uint2*)&As[r * AST2 + kb + t * 2];
                uint2 hi = *(const uint2*)&As[(r + 8) * AST2 + kb + t * 2];
                af[mt][0] = lo.x; af[mt][2] = lo.y;
                af[mt][1] = hi.x; af[mt][3] = hi.y;
            }
#pragma unroll
            for (int nt = 0; nt < 4; nt++) {
                int cn = wn0 + nt * 8 + g;
                bf[nt][0] = Bs[(kb + t) * GST + cn];
                bf[nt][1] = Bs[(kb + t + 4) * GST + cn];
            }
#pragma unroll
            for (int mt = 0; mt < 4; mt++)
#pragma unroll
                for (int nt = 0; nt < 4; nt++)
                    mma_tf32(acc[mt][nt], af[mt], bf[nt]);
        }
        __syncthreads();
    }

#pragma unroll
    for (int mt = 0; mt < 4; mt++) {
        int r = bm0 + wm0 + mt * 16 + g;
#pragma unroll
        for (int nt = 0; nt < 4; nt++) {
            int col = bn0 + wn0 + nt * 8 + t * 2;
            float b0 = bias[col], b1 = bias[col + 1];
            *(float2*)(C + (size_t)r * 512 + col) =
                make_float2(acc[mt][nt][0] + b0, acc[mt][nt][1] + b1);
            *(float2*)(C + (size_t)(r + 8) * 512 + col) =
                make_float2(acc[mt][nt][2] + b0, acc[mt][nt][3] + b1);
        }
    }
}

// ---------------------------------------------------------------------------
// Flash attention (causal), tf32 mma.
// Block: 128 threads = 4 warps; 128 q-rows/block, 32 rows/warp (2 m16 subtiles,
// sharing every K/V b-fragment).  KV tile = 32 keys (keeps s[] at 32 regs ->
// no spills).  Q fragments register-resident.  Pair-permuted smem:
//   sK: [keyrow][perm(col)]   32 x 72 words
//   sV: [col][perm(keyrow)]   64 x 40 words
//   sP: [qrow][perm(key)]     128 x 40 words, per-warp private
// All fragment loads are LDS.64, conflict-free per half-warp.
// ---------------------------------------------------------------------------
#define AKST 72
#define PST  40

__global__ __launch_bounds__(128)
void attn_tf32_kernel()
{
    __shared__ __align__(16) unsigned sK[32 * AKST];
    __shared__ __align__(16) unsigned sV[64 * PST];
    __shared__ __align__(16) unsigned sP[128 * PST];

    const int tid  = threadIdx.x;
    const int lane = tid & 31;
    const int w    = tid >> 5;
    const int g    = lane >> 2;
    const int t    = lane & 3;

    const int qt  = gridDim.x - 1 - blockIdx.x;  // heavy tiles first
    const int q0  = qt * 128;
    const int b   = blockIdx.y >> 3;
    const int h   = blockIdx.y & 7;
    const int wq  = w * 32;

    // Q fragments for both subtiles, scale 0.125 folded in
    unsigned qf[2][8][4];
    {
        const float* qp = g_q + (size_t)(b * S_ + q0 + wq) * 512 + h * 64;
#pragma unroll
        for (int su = 0; su < 2; su++)
#pragma unroll
            for (int c = 0; c < 8; c++) {
                int r0 = su * 16 + g;
                qf[su][c][0] = f2tf(0.125f * qp[(size_t)r0 * 512 + c * 8 + t]);
                qf[su][c][1] = f2tf(0.125f * qp[(size_t)(r0 + 8) * 512 + c * 8 + t]);
                qf[su][c][2] = f2tf(0.125f * qp[(size_t)r0 * 512 + c * 8 + t + 4]);
                qf[su][c][3] = f2tf(0.125f * qp[(size_t)(r0 + 8) * 512 + c * 8 + t + 4]);
            }
    }

    float o[2][8][4];
#pragma unroll
    for (int su = 0; su < 2; su++)
#pragma unroll
        for (int nt = 0; nt < 8; nt++)
#pragma unroll
            for (int i = 0; i < 4; i++) o[su][nt][i] = 0.f;
    float mst[2][2] = {{-1e30f, -1e30f}, {-1e30f, -1e30f}};
    float lst[2][2] = {{0.f, 0.f}, {0.f, 0.f}};

    const int p0slot = (t & 1) * 4 + (t >> 1);

    for (int j0 = 0; j0 < q0 + 128; j0 += 32) {
        __syncthreads();   // prior tile's fragment reads complete
        // ---- fill K (32x64) and V (32x64) tiles ----
        {
            const float* kp = g_k + (size_t)(b * S_ + j0) * 512 + h * 64;
            const float* vp = g_v + (size_t)(b * S_ + j0) * 512 + h * 64;
#pragma unroll
            for (int i = 0; i < 2; i++) {
                int ch = tid + i * 128;          // 0..255
                int r  = ch >> 3;                // key row 0..31
                int a  = ch & 7;                 // 8-col chunk
                const float* kr = kp + (size_t)r * 512 + a * 8;
                float4 k0 = *(const float4*)kr;
                float4 k1 = *(const float4*)(kr + 4);
                *(uint4*)&sK[r * AKST + a * 8 + 0] =
                    make_uint4(f2tf(k0.x), f2tf(k1.x), f2tf(k0.y), f2tf(k1.y));
                *(uint4*)&sK[r * AKST + a * 8 + 4] =
                    make_uint4(f2tf(k0.z), f2tf(k1.z), f2tf(k0.w), f2tf(k1.w));
                const float* vr = vp + (size_t)r * 512 + a * 8;
                float4 v0 = *(const float4*)vr;
                float4 v1 = *(const float4*)(vr + 4);
                int rp = (r >> 3) * 8 + (r & 3) * 2 + ((r >> 2) & 1);
                sV[(a * 8 + 0) * PST + rp] = f2tf(v0.x);
                sV[(a * 8 + 1) * PST + rp] = f2tf(v0.y);
                sV[(a * 8 + 2) * PST + rp] = f2tf(v0.z);
                sV[(a * 8 + 3) * PST + rp] = f2tf(v0.w);
                sV[(a * 8 + 4) * PST + rp] = f2tf(v1.x);
                sV[(a * 8 + 5) * PST + rp] = f2tf(v1.y);
                sV[(a * 8 + 6) * PST + rp] = f2tf(v1.z);
                sV[(a * 8 + 7) * PST + rp] = f2tf(v1.w);
            }
        }
        __syncthreads();

        if (j0 > q0 + wq + 31) continue;   // tile fully above this warp's diagonal

        // ---- S = Q @ K^T  (32 rows x 32 keys per warp) ----
        float s[2][4][4];
#pragma unroll
        for (int su = 0; su < 2; su++)
#pragma unroll
            for (int nt = 0; nt < 4; nt++)
#pragma unroll
                for (int i = 0; i < 4; i++) s[su][nt][i] = 0.f;
#pragma unroll
        for (int c = 0; c < 8; c++)
#pragma unroll
            for (int nt = 0; nt < 4; nt++) {
                uint2 bv = *(const uint2*)&sK[(nt * 8 + g) * AKST + c * 8 + t * 2];
                unsigned bf[2] = {bv.x, bv.y};
                mma_tf32(s[0][nt], qf[0][c], bf);
                mma_tf32(s[1][nt], qf[1][c], bf);
            }

        // ---- causal mask (diagonal-overlapping tiles) ----
        if (j0 + 31 > q0 + wq) {
#pragma unroll
            for (int su = 0; su < 2; su++) {
                int r0 = q0 + wq + su * 16 + g;
#pragma unroll
                for (int nt = 0; nt < 4; nt++) {
                    int c0 = j0 + nt * 8 + t * 2;
                    if (c0     > r0)     s[su][nt][0] = -1e30f;
                    if (c0 + 1 > r0)     s[su][nt][1] = -1e30f;
                    if (c0     > r0 + 8) s[su][nt][2] = -1e30f;
                    if (c0 + 1 > r0 + 8) s[su][nt][3] = -1e30f;
                }
            }
        }

        // ---- online softmax + P write (per-warp private sP rows) ----
#pragma unroll
        for (int su = 0; su < 2; su++) {
            float mx0 = -1e30f, mx1 = -1e30f;
#pragma unroll
            for (int nt = 0; nt < 4; nt++) {
                mx0 = fmaxf(mx0, fmaxf(s[su][nt][0], s[su][nt][1]));
                mx1 = fmaxf(mx1, fmaxf(s[su][nt][2], s[su][nt][3]));
            }
            mx0 = fmaxf(mx0, __shfl_xor_sync(0xffffffffu, mx0, 1));
            mx0 = fmaxf(mx0, __shfl_xor_sync(0xffffffffu, mx0, 2));
            mx1 = fmaxf(mx1, __shfl_xor_sync(0xffffffffu, mx1, 1));
            mx1 = fmaxf(mx1, __shfl_xor_sync(0xffffffffu, mx1, 2));
            float nm0 = fmaxf(mst[su][0], mx0), nm1 = fmaxf(mst[su][1], mx1);
            float cor0 = __expf(mst[su][0] - nm0), cor1 = __expf(mst[su][1] - nm1);
            mst[su][0] = nm0; mst[su][1] = nm1;

            float ls0 = 0.f, ls1 = 0.f;
            int rowA = (wq + su * 16 + g) * PST;
            int rowB = rowA + 8 * PST;
#pragma unroll
            for (int nt = 0; nt < 4; nt++) {
                float e0 = __expf(s[su][nt][0] - nm0);
                float e1 = __expf(s[su][nt][1] - nm0);
                float e2 = __expf(s[su][nt][2] - nm1);
                float e3 = __expf(s[su][nt][3] - nm1);
                ls0 += e0 + e1; ls1 += e2 + e3;
                sP[rowA + nt * 8 + p0slot]     = f2tf(e0);
                sP[rowA + nt * 8 + p0slot + 2] = f2tf(e1);
                sP[rowB + nt * 8 + p0slot]     = f2tf(e2);
                sP[rowB + nt * 8 + p0slot + 2] = f2tf(e3);
            }
            ls0 += __shfl_xor_sync(0xffffffffu, ls0, 1);
            ls0 += __shfl_xor_sync(0xffffffffu, ls0, 2);
            ls1 += __shfl_xor_sync(0xffffffffu, ls1, 1);
            ls1 += __shfl_xor_sync(0xffffffffu, ls1, 2);
            lst[su][0] = lst[su][0] * cor0 + ls0;
            lst[su][1] = lst[su][1] * cor1 + ls1;

#pragma unroll
            for (int nt = 0; nt < 8; nt++) {
                o[su][nt][0] *= cor0; o[su][nt][1] *= cor0;
                o[su][nt][2] *= cor1; o[su][nt][3] *= cor1;
            }
        }
        __syncwarp();

        // ---- O += P @ V ----
#pragma unroll
        for (int c = 0; c < 4; c++) {
            unsigned pa[2][4];
#pragma unroll
            for (int su = 0; su < 2; su++) {
                uint2 lo = *(const uint2*)&sP[(wq + su * 16 + g) * PST + c * 8 + t * 2];
                uint2 hi = *(const uint2*)&sP[(wq + su * 16 + g + 8) * PST + c * 8 + t * 2];
                pa[su][0] = lo.x; pa[su][2] = lo.y;
                pa[su][1] = hi.x; pa[su][3] = hi.y;
            }
#pragma unroll
            for (int nt = 0; nt < 8; nt++) {
                uint2 bv = *(const uint2*)&sV[(nt * 8 + g) * PST + c * 8 + t * 2];
                unsigned bf[2] = {bv.x, bv.y};
                mma_tf32(o[0][nt], pa[0], bf);
                mma_tf32(o[1][nt], pa[1], bf);
            }
        }
    }

    // ---- normalize + store (concat layout [B*S, H*64]) ----
    float* op = g_ctx + (size_t)(b * S_ + q0 + wq) * 512 + h * 64;
#pragma unroll
    for (int su = 0; su < 2; su++) {
        float inv0 = 1.f / lst[su][0], inv1 = 1.f / lst[su][1];
        int r0 = su * 16 + g;
#pragma unroll
        for (int nt = 0; nt < 8; nt++) {
            int col = nt * 8 + t * 2;
            *(float2*)(op + (size_t)r0 * 512 + col) =
                make_float2(o[su][nt][0] * inv0, o[su][nt][1] * inv0);
            *(float2*)(op + (size_t)(r0 + 8) * 512 + col) =
                make_float2(o[su][nt][2] * inv1, o[su][nt][3] * inv1);
        }
    }
}

// ---------------------------------------------------------------------------
// Launch.  inputs: 0 Q,1 K,2 V,3 mask(all-true),4 Wq,5 bq,6 Wk,7 bk,
//                  8 Wv,9 bv,10 Wo,11 bo
// ---------------------------------------------------------------------------
extern "C" void kernel_launch(void* const* d_in, const int* in_sizes, int n_in,
                              void* d_out, int out_size)
{
    const float* Q  = (const float*)d_in[0];
    const float* K  = (const float*)d_in[1];
    const float* V  = (const float*)d_in[2];
    const float* Wq = (const float*)d_in[4];
    const float* bq = (const float*)d_in[5];
    const float* Wk = (const float*)d_in[6];
    const float* bk = (const float*)d_in[7];
    const float* Wv = (const float*)d_in[8];
    const float* bv = (const float*)d_in[9];
    const float* Wo = (const float*)d_in[10];
    const float* bo = (const float*)d_in[11];
    float* out = (float*)d_out;

    dim3 gg(M_ / GBM, NW_ / GBN);   // 64 x 4

    gemm_tf32_kernel<true><<<gg, 256>>>(Q, Wq, bq, nullptr, 0, 0);
    gemm_tf32_kernel<true><<<gg, 256>>>(K, Wk, bk, nullptr, 0, 1);
    gemm_tf32_kernel<true><<<gg, 256>>>(V, Wv, bv, nullptr, 0, 2);

    dim3 ga(S_ / 128, B_ * H_);     // 16 x 32
    attn_tf32_kernel<<<ga, 128>>>();

    gemm_tf32_kernel<false><<<gg, 256>>>(nullptr, Wo, bo, out, 1, 3);
}

// round 5
// speedup vs baseline: 1.0967x; 1.0967x over previous
#include <cuda_runtime.h>
#include <cstdint>

// Problem constants
#define B_  4
#define S_  2048
#define D_  512
#define H_  8
#define HD_ 64
#define M_  (B_*S_)       // 8192
#define NW_ 512

// Scratch (device globals)
__device__ float g_q[M_ * NW_];
__device__ float g_k[M_ * NW_];
__device__ float g_v[M_ * NW_];
__device__ float g_ctx[M_ * NW_];

__device__ __forceinline__ unsigned f2tf(float f) {
    unsigned u;
    asm("cvt.rna.tf32.f32 %0, %1;" : "=r"(u) : "f"(f));
    return u;
}

__device__ __forceinline__ void mma_tf32(float* c, const unsigned* a, const unsigned* b) {
    asm volatile("mma.sync.aligned.m16n8k8.row.col.f32.tf32.tf32.f32 "
        "{%0,%1,%2,%3}, {%4,%5,%6,%7}, {%8,%9}, {%0,%1,%2,%3};"
        : "+f"(c[0]), "+f"(c[1]), "+f"(c[2]), "+f"(c[3])
        : "r"(a[0]), "r"(a[1]), "r"(a[2]), "r"(a[3]), "r"(b[0]), "r"(b[1]));
}

// ---------------------------------------------------------------------------
// tf32 GEMM: C[8192,512] = A[8192,512] @ W(512,512) + bias[512]
// QKV=true: gridDim.z=3 selects (Q,Wq,bq)->g_q etc, W layout [H,D,64].
// QKV=false: A=g_ctx, W row-major [512,512], C=Cout.
// Block 128x128x16, 256 threads, 8 warps (2m x 4n), warp tile 64x32.
// ---------------------------------------------------------------------------
#define GBM 128
#define GBN 128
#define GBK 16
#define AST2 24
#define GST 136

template<bool QKV>
__global__ __launch_bounds__(256)
void gemm_tf32_kernel(const float* __restrict__ A0,
                      const float* __restrict__ A1,
                      const float* __restrict__ A2,
                      const float* __restrict__ W0,
                      const float* __restrict__ W1,
                      const float* __restrict__ W2,
                      const float* __restrict__ b0p,
                      const float* __restrict__ b1p,
                      const float* __restrict__ b2p,
                      float* __restrict__ Cout)
{
    const float* A;
    const float* W;
    const float* bias;
    float* C;
    if (QKV) {
        int z = blockIdx.z;
        A    = (z == 0) ? A0 : (z == 1) ? A1 : A2;
        W    = (z == 0) ? W0 : (z == 1) ? W1 : W2;
        bias = (z == 0) ? b0p : (z == 1) ? b1p : b2p;
        C    = (z == 0) ? g_q : (z == 1) ? g_k : g_v;
    } else {
        A = g_ctx; W = W0; bias = b0p; C = Cout;
    }

    __shared__ __align__(16) unsigned As[GBM * AST2];
    __shared__ __align__(16) unsigned Bs[GBK * GST];

    const int tid  = threadIdx.x;
    const int lane = tid & 31;
    const int w    = tid >> 5;
    const int g    = lane >> 2;
    const int t    = lane & 3;

    const int bm0 = blockIdx.x * GBM;
    const int bn0 = blockIdx.y * GBN;
    const int wm0 = (w & 1) * 64;
    const int wn0 = (w >> 1) * 32;

    const int aRow = tid >> 1;
    const int aK   = (tid & 1) * 8;
    const int bK   = tid >> 4;
    const int bN   = (tid & 15) * 8;

    float acc[4][4][4];
#pragma unroll
    for (int mt = 0; mt < 4; mt++)
#pragma unroll
        for (int nt = 0; nt < 4; nt++)
#pragma unroll
            for (int i = 0; i < 4; i++) acc[mt][nt][i] = 0.f;

    for (int k0 = 0; k0 < 512; k0 += GBK) {
        {
            const float* ap = A + (size_t)(bm0 + aRow) * 512 + k0 + aK;
            float4 a0 = *(const float4*)ap;
            float4 a1 = *(const float4*)(ap + 4);
            uint4 u0 = make_uint4(f2tf(a0.x), f2tf(a1.x), f2tf(a0.y), f2tf(a1.y));
            uint4 u1 = make_uint4(f2tf(a0.z), f2tf(a1.z), f2tf(a0.w), f2tf(a1.w));
            *(uint4*)&As[aRow * AST2 + aK + 0] = u0;
            *(uint4*)&As[aRow * AST2 + aK + 4] = u1;
        }
#pragma unroll
        for (int j = 0; j < 2; j++) {
            int n = bn0 + bN + j * 4;
            const float* bp;
            if (QKV) bp = W + (size_t)(n >> 6) * (D_ * 64) + (size_t)(k0 + bK) * 64 + (n & 63);
            else     bp = W + (size_t)(k0 + bK) * 512 + n;
            float4 bv = *(const float4*)bp;
            Bs[bK * GST + bN + j * 4 + 0] = f2tf(bv.x);
            Bs[bK * GST + bN + j * 4 + 1] = f2tf(bv.y);
            Bs[bK * GST + bN + j * 4 + 2] = f2tf(bv.z);
            Bs[bK * GST + bN + j * 4 + 3] = f2tf(bv.w);
        }
        __syncthreads();

#pragma unroll
        for (int kc = 0; kc < 2; kc++) {
            const int kb = kc * 8;
            unsigned af[4][4], bf[4][2];
#pragma unroll
            for (int mt = 0; mt < 4; mt++) {
                int r = wm0 + mt * 16 + g;
                uint2 lo = *(const uint2*)&As[r * AST2 + kb + t * 2];
                uint2 hi = *(const uint2*)&As[(r + 8) * AST2 + kb + t * 2];
                af[mt][0] = lo.x; af[mt][2] = lo.y;
                af[mt][1] = hi.x; af[mt][3] = hi.y;
            }
#pragma unroll
            for (int nt = 0; nt < 4; nt++) {
                int cn = wn0 + nt * 8 + g;
                bf[nt][0] = Bs[(kb + t) * GST + cn];
                bf[nt][1] = Bs[(kb + t + 4) * GST + cn];
            }
#pragma unroll
            for (int mt = 0; mt < 4; mt++)
#pragma unroll
                for (int nt = 0; nt < 4; nt++)
                    mma_tf32(acc[mt][nt], af[mt], bf[nt]);
        }
        __syncthreads();
    }

#pragma unroll
    for (int mt = 0; mt < 4; mt++) {
        int r = bm0 + wm0 + mt * 16 + g;
#pragma unroll
        for (int nt = 0; nt < 4; nt++) {
            int col = bn0 + wn0 + nt * 8 + t * 2;
            float bb0 = bias[col], bb1 = bias[col + 1];
            *(float2*)(C + (size_t)r * 512 + col) =
                make_float2(acc[mt][nt][0] + bb0, acc[mt][nt][1] + bb1);
            *(float2*)(C + (size_t)(r + 8) * 512 + col) =
                make_float2(acc[mt][nt][2] + bb0, acc[mt][nt][3] + bb1);
        }
    }
}

// ---------------------------------------------------------------------------
// Flash attention (causal), tf32 mma.
// Block: 4 warps, 64 q-rows (16/warp), KV tile = 64 keys.
//   sK: [keyrow][perm(col)]  64 x 72, pair-permuted cols, STS.128 fill,
//       uint2 b-frags (conflict-free).
//   sV: [keyrow][col] K-major 64 x 72, STS.128 fill, scalar b-frags
//       (banks 8t+g, conflict-free).
//   sP: [qrow][perm(key)] 64 x 72, per-warp private (syncwarp only).
// Q fragments register-resident, scale folded.
// ---------------------------------------------------------------------------
#define AKST 72

__global__ __launch_bounds__(128, 3)
void attn_tf32_kernel()
{
    extern __shared__ __align__(16) unsigned smem[];
    unsigned* sK = smem;                 // 64*72
    unsigned* sV = smem + 64 * AKST;     // 64*72
    unsigned* sP = smem + 128 * AKST;    // 64*72

    const int tid  = threadIdx.x;
    const int lane = tid & 31;
    const int w    = tid >> 5;
    const int g    = lane >> 2;
    const int t    = lane & 3;

    const int qt  = gridDim.x - 1 - blockIdx.x;  // heavy tiles first
    const int q0  = qt * 64;
    const int b   = blockIdx.y >> 3;
    const int h   = blockIdx.y & 7;
    const int wq  = w * 16;

    // Q fragments (scale 0.125 folded in), register resident
    unsigned qf[8][4];
    {
        const float* qp = g_q + (size_t)(b * S_ + q0 + wq) * 512 + h * 64;
#pragma unroll
        for (int c = 0; c < 8; c++) {
            qf[c][0] = f2tf(0.125f * qp[(size_t)g * 512 + c * 8 + t]);
            qf[c][1] = f2tf(0.125f * qp[(size_t)(g + 8) * 512 + c * 8 + t]);
            qf[c][2] = f2tf(0.125f * qp[(size_t)g * 512 + c * 8 + t + 4]);
            qf[c][3] = f2tf(0.125f * qp[(size_t)(g + 8) * 512 + c * 8 + t + 4]);
        }
    }

    float o[8][4];
#pragma unroll
    for (int nt = 0; nt < 8; nt++)
#pragma unroll
        for (int i = 0; i < 4; i++) o[nt][i] = 0.f;
    float m0 = -1e30f, m1 = -1e30f, l0 = 0.f, l1 = 0.f;

    const int p0slot = (t & 1) * 4 + (t >> 1);

    for (int j0 = 0; j0 < q0 + 64; j0 += 64) {
        __syncthreads();   // prior tile's fragment reads complete
        // ---- fill K (pair-permuted) and V (K-major) tiles, all STS.128 ----
        {
            const float* kp = g_k + (size_t)(b * S_ + j0) * 512 + h * 64;
            const float* vp = g_v + (size_t)(b * S_ + j0) * 512 + h * 64;
#pragma unroll
            for (int i = 0; i < 4; i++) {
                int ch = tid + i * 128;          // 0..511
                int r  = ch >> 3;                // key row 0..63
                int a  = ch & 7;                 // 8-col chunk
                const float* kr = kp + (size_t)r * 512 + a * 8;
                float4 k0 = *(const float4*)kr;
                float4 k1 = *(const float4*)(kr + 4);
                *(uint4*)&sK[r * AKST + a * 8 + 0] =
                    make_uint4(f2tf(k0.x), f2tf(k1.x), f2tf(k0.y), f2tf(k1.y));
                *(uint4*)&sK[r * AKST + a * 8 + 4] =
                    make_uint4(f2tf(k0.z), f2tf(k1.z), f2tf(k0.w), f2tf(k1.w));
                const float* vr = vp + (size_t)r * 512 + a * 8;
                float4 v0 = *(const float4*)vr;
                float4 v1 = *(const float4*)(vr + 4);
                *(uint4*)&sV[r * AKST + a * 8 + 0] =
                    make_uint4(f2tf(v0.x), f2tf(v0.y), f2tf(v0.z), f2tf(v0.w));
                *(uint4*)&sV[r * AKST + a * 8 + 4] =
                    make_uint4(f2tf(v1.x), f2tf(v1.y), f2tf(v1.z), f2tf(v1.w));
            }
        }
        __syncthreads();

        if (j0 > q0 + wq + 15) continue;   // tile fully above this warp's rows

        // ---- S = Q @ K^T (16 rows x 64 keys) ----
        float s[8][4];
#pragma unroll
        for (int nt = 0; nt < 8; nt++)
#pragma unroll
            for (int i = 0; i < 4; i++) s[nt][i] = 0.f;
#pragma unroll
        for (int c = 0; c < 8; c++)
#pragma unroll
            for (int nt = 0; nt < 8; nt++) {
                uint2 bv = *(const uint2*)&sK[(nt * 8 + g) * AKST + c * 8 + t * 2];
                unsigned bf[2] = {bv.x, bv.y};
                mma_tf32(s[nt], qf[c], bf);
            }

        // ---- causal mask (diagonal-overlapping tiles only) ----
        if (j0 + 63 > q0 + wq) {
            int r0 = q0 + wq + g;
#pragma unroll
            for (int nt = 0; nt < 8; nt++) {
                int c0 = j0 + nt * 8 + t * 2;
                if (c0     > r0)     s[nt][0] = -1e30f;
                if (c0 + 1 > r0)     s[nt][1] = -1e30f;
                if (c0     > r0 + 8) s[nt][2] = -1e30f;
                if (c0 + 1 > r0 + 8) s[nt][3] = -1e30f;
            }
        }

        // ---- online softmax ----
        float mx0 = -1e30f, mx1 = -1e30f;
#pragma unroll
        for (int nt = 0; nt < 8; nt++) {
            mx0 = fmaxf(mx0, fmaxf(s[nt][0], s[nt][1]));
            mx1 = fmaxf(mx1, fmaxf(s[nt][2], s[nt][3]));
        }
        mx0 = fmaxf(mx0, __shfl_xor_sync(0xffffffffu, mx0, 1));
        mx0 = fmaxf(mx0, __shfl_xor_sync(0xffffffffu, mx0, 2));
        mx1 = fmaxf(mx1, __shfl_xor_sync(0xffffffffu, mx1, 1));
        mx1 = fmaxf(mx1, __shfl_xor_sync(0xffffffffu, mx1, 2));
        float nm0 = fmaxf(m0, mx0), nm1 = fmaxf(m1, mx1);
        float cor0 = __expf(m0 - nm0), cor1 = __expf(m1 - nm1);
        m0 = nm0; m1 = nm1;

        float ls0 = 0.f, ls1 = 0.f;
        {
            int rowA = (wq + g) * AKST;
            int rowB = rowA + 8 * AKST;
#pragma unroll
            for (int nt = 0; nt < 8; nt++) {
                float e0 = __expf(s[nt][0] - nm0);
                float e1 = __expf(s[nt][1] - nm0);
                float e2 = __expf(s[nt][2] - nm1);
                float e3 = __expf(s[nt][3] - nm1);
                ls0 += e0 + e1; ls1 += e2 + e3;
                sP[rowA + nt * 8 + p0slot]     = f2tf(e0);
                sP[rowA + nt * 8 + p0slot + 2] = f2tf(e1);
                sP[rowB + nt * 8 + p0slot]     = f2tf(e2);
                sP[rowB + nt * 8 + p0slot + 2] = f2tf(e3);
            }
        }
        ls0 += __shfl_xor_sync(0xffffffffu, ls0, 1);
        ls0 += __shfl_xor_sync(0xffffffffu, ls0, 2);
        ls1 += __shfl_xor_sync(0xffffffffu, ls1, 1);
        ls1 += __shfl_xor_sync(0xffffffffu, ls1, 2);
        l0 = l0 * cor0 + ls0;
        l1 = l1 * cor1 + ls1;

#pragma unroll
        for (int nt = 0; nt < 8; nt++) {
            o[nt][0] *= cor0; o[nt][1] *= cor0;
            o[nt][2] *= cor1; o[nt][3] *= cor1;
        }
        __syncwarp();   // P visible across this warp

        // ---- O += P @ V ----
#pragma unroll
        for (int c = 0; c < 8; c++) {
            unsigned pa[4];
            uint2 lo = *(const uint2*)&sP[(wq + g) * AKST + c * 8 + t * 2];
            uint2 hi = *(const uint2*)&sP[(wq + g + 8) * AKST + c * 8 + t * 2];
            pa[0] = lo.x; pa[2] = lo.y;
            pa[1] = hi.x; pa[3] = hi.y;
#pragma unroll
            for (int nt = 0; nt < 8; nt++) {
                unsigned bf[2];
                bf[0] = sV[(c * 8 + t) * AKST + nt * 8 + g];
                bf[1] = sV[(c * 8 + t + 4) * AKST + nt * 8 + g];
                mma_tf32(o[nt], pa, bf);
            }
        }
    }

    // ---- normalize + store (concat layout [B*S, H*64]) ----
    float inv0 = 1.f / l0, inv1 = 1.f / l1;
    float* op = g_ctx + (size_t)(b * S_ + q0 + wq) * 512 + h * 64;
#pragma unroll
    for (int nt = 0; nt < 8; nt++) {
        int col = nt * 8 + t * 2;
        *(float2*)(op + (size_t)g * 512 + col) =
            make_float2(o[nt][0] * inv0, o[nt][1] * inv0);
        *(float2*)(op + (size_t)(g + 8) * 512 + col) =
            make_float2(o[nt][2] * inv1, o[nt][3] * inv1);
    }
}

#define ATTN_SMEM (192 * AKST * 4)   // 55296 bytes

// ---------------------------------------------------------------------------
// Launch.  inputs: 0 Q,1 K,2 V,3 mask(all-true),4 Wq,5 bq,6 Wk,7 bk,
//                  8 Wv,9 bv,10 Wo,11 bo
// ---------------------------------------------------------------------------
extern "C" void kernel_launch(void* const* d_in, const int* in_sizes, int n_in,
                              void* d_out, int out_size)
{
    const float* Q  = (const float*)d_in[0];
    const float* K  = (const float*)d_in[1];
    const float* V  = (const float*)d_in[2];
    const float* Wq = (const float*)d_in[4];
    const float* bq = (const float*)d_in[5];
    const float* Wk = (const float*)d_in[6];
    const float* bk = (const float*)d_in[7];
    const float* Wv = (const float*)d_in[8];
    const float* bv = (const float*)d_in[9];
    const float* Wo = (const float*)d_in[10];
    const float* bo = (const float*)d_in[11];
    float* out = (float*)d_out;

    cudaFuncSetAttribute(attn_tf32_kernel,
                         cudaFuncAttributeMaxDynamicSharedMemorySize, ATTN_SMEM);

    // QKV projections in one launch (z selects Q/K/V)
    dim3 gq(M_ / GBM, NW_ / GBN, 3);   // 64 x 4 x 3
    gemm_tf32_kernel<true><<<gq, 256>>>(Q, K, V, Wq, Wk, Wv, bq, bk, bv, nullptr);

    // Causal attention
    dim3 ga(S_ / 64, B_ * H_);         // 32 x 32
    attn_tf32_kernel<<<ga, 128, ATTN_SMEM>>>();

    // Output projection
    dim3 gg(M_ / GBM, NW_ / GBN);      // 64 x 4
    gemm_tf32_kernel<false><<<gg, 256>>>(nullptr, nullptr, nullptr,
                                         Wo, nullptr, nullptr,
                                         bo, nullptr, nullptr, out);
}

// round 6
// speedup vs baseline: 1.2192x; 1.1117x over previous
#include <cuda_runtime.h>
#include <cstdint>

// Problem constants
#define B_  4
#define S_  2048
#define D_  512
#define H_  8
#define HD_ 64
#define M_  (B_*S_)       // 8192
#define NW_ 512

// Scratch (device globals)
__device__ float g_q[M_ * NW_];
__device__ float g_k[M_ * NW_];
__device__ float g_v[M_ * NW_];
__device__ float g_ctx[M_ * NW_];

__device__ __forceinline__ unsigned f2tf(float f) {
    unsigned u;
    asm("cvt.rna.tf32.f32 %0, %1;" : "=r"(u) : "f"(f));
    return u;
}

__device__ __forceinline__ void mma_tf32(float* c, const unsigned* a, const unsigned* b) {
    asm volatile("mma.sync.aligned.m16n8k8.row.col.f32.tf32.tf32.f32 "
        "{%0,%1,%2,%3}, {%4,%5,%6,%7}, {%8,%9}, {%0,%1,%2,%3};"
        : "+f"(c[0]), "+f"(c[1]), "+f"(c[2]), "+f"(c[3])
        : "r"(a[0]), "r"(a[1]), "r"(a[2]), "r"(a[3]), "r"(b[0]), "r"(b[1]));
}

__device__ __forceinline__ void cpa16(void* sptr, const void* g) {
    unsigned sa = (unsigned)__cvta_generic_to_shared(sptr);
    asm volatile("cp.async.cg.shared.global [%0], [%1], 16;" :: "r"(sa), "l"(g));
}
#define CP_COMMIT() asm volatile("cp.async.commit_group;" ::: "memory")
#define CP_WAIT0()  asm volatile("cp.async.wait_group 0;" ::: "memory")

// ---------------------------------------------------------------------------
// tf32 GEMM, cp.async double-buffered.
// C[8192,512] = A[8192,512] @ W(512,512) + bias[512]
// QKV=true: gridDim.z selects (Q,Wq,bq)->g_q etc; W layout [H,D,64].
// QKV=false: A=g_ctx, W row-major, C=Cout.
// Block 128x128x16, 256 threads, 8 warps (2m x 4n), warp tile 64x32.
// smem raw fp32; tf32 cvt at fragment build.
//   As[st][128][20]: frag addr r*20+k -> banks 20g+t (all 32 distinct)
//   Bs[st][16][136]: frag addr k*136+cn -> banks 8t+g+8nt (all 32 distinct)
// ---------------------------------------------------------------------------
#define GBM 128
#define GBN 128
#define GBK 16
#define ASTR 20
#define BSTR 136

template<bool QKV>
__global__ __launch_bounds__(256, 2)
void gemm_tf32_kernel(const float* __restrict__ A0,
                      const float* __restrict__ A1,
                      const float* __restrict__ A2,
                      const float* __restrict__ W0,
                      const float* __restrict__ W1,
                      const float* __restrict__ W2,
                      const float* __restrict__ b0p,
                      const float* __restrict__ b1p,
                      const float* __restrict__ b2p,
                      float* __restrict__ Cout)
{
    const float* A; const float* W; const float* bias; float* C;
    if (QKV) {
        int z = blockIdx.z;
        A    = (z == 0) ? A0 : (z == 1) ? A1 : A2;
        W    = (z == 0) ? W0 : (z == 1) ? W1 : W2;
        bias = (z == 0) ? b0p : (z == 1) ? b1p : b2p;
        C    = (z == 0) ? g_q : (z == 1) ? g_k : g_v;
    } else {
        A = g_ctx; W = W0; bias = b0p; C = Cout;
    }

    __shared__ __align__(16) float As[2][GBM * ASTR];
    __shared__ __align__(16) float Bs[2][GBK * BSTR];

    const int tid  = threadIdx.x;
    const int lane = tid & 31;
    const int w    = tid >> 5;
    const int g    = lane >> 2;
    const int t    = lane & 3;

    const int bm0 = blockIdx.x * GBM;
    const int bn0 = blockIdx.y * GBN;
    const int wm0 = (w & 1) * 64;
    const int wn0 = (w >> 1) * 32;

    // prefetch mappings
    const int aRow = tid >> 1;          // 0..127
    const int aK   = (tid & 1) * 8;     // 0 or 8
    const int bR   = tid >> 4;          // 0..15
    const int bN   = (tid & 15) * 4;    // 0..60

    float acc[4][4][4];
#pragma unroll
    for (int mt = 0; mt < 4; mt++)
#pragma unroll
        for (int nt = 0; nt < 4; nt++)
#pragma unroll
            for (int i = 0; i < 4; i++) acc[mt][nt][i] = 0.f;

    // prefetch helper (as lambda-free macro-ish)
    auto prefetch = [&](int st, int k0) {
        const float* ap = A + (size_t)(bm0 + aRow) * 512 + k0 + aK;
        cpa16(&As[st][aRow * ASTR + aK], ap);
        cpa16(&As[st][aRow * ASTR + aK + 4], ap + 4);
#pragma unroll
        for (int j = 0; j < 2; j++) {
            int n = bn0 + bN + j * 64;
            const float* bp;
            if (QKV) bp = W + (size_t)(n >> 6) * (D_ * 64) + (size_t)(k0 + bR) * 64 + (n & 63);
            else     bp = W + (size_t)(k0 + bR) * 512 + n;
            cpa16(&Bs[st][bR * BSTR + bN + j * 64], bp);
        }
    };

    prefetch(0, 0);
    CP_COMMIT();

    for (int it = 0; it < 32; it++) {
        const int st = it & 1;
        CP_WAIT0();
        __syncthreads();
        if (it + 1 < 32) prefetch(st ^ 1, (it + 1) * GBK);
        CP_COMMIT();

#pragma unroll
        for (int kc = 0; kc < 16; kc += 8) {
            unsigned af[4][4], bf[4][2];
#pragma unroll
            for (int mt = 0; mt < 4; mt++) {
                int r = wm0 + mt * 16 + g;
                const float* ar  = &As[st][r * ASTR + kc + t];
                const float* ar8 = ar + 8 * ASTR;
                af[mt][0] = f2tf(ar[0]);
                af[mt][2] = f2tf(ar[4]);
                af[mt][1] = f2tf(ar8[0]);
                af[mt][3] = f2tf(ar8[4]);
            }
#pragma unroll
            for (int nt = 0; nt < 4; nt++) {
                int cn = wn0 + nt * 8 + g;
                bf[nt][0] = f2tf(Bs[st][(kc + t) * BSTR + cn]);
                bf[nt][1] = f2tf(Bs[st][(kc + t + 4) * BSTR + cn]);
            }
#pragma unroll
            for (int mt = 0; mt < 4; mt++)
#pragma unroll
                for (int nt = 0; nt < 4; nt++)
                    mma_tf32(acc[mt][nt], af[mt], bf[nt]);
        }
    }

#pragma unroll
    for (int mt = 0; mt < 4; mt++) {
        int r = bm0 + wm0 + mt * 16 + g;
#pragma unroll
        for (int nt = 0; nt < 4; nt++) {
            int col = bn0 + wn0 + nt * 8 + t * 2;
            float bb0 = bias[col], bb1 = bias[col + 1];
            *(float2*)(C + (size_t)r * 512 + col) =
                make_float2(acc[mt][nt][0] + bb0, acc[mt][nt][1] + bb1);
            *(float2*)(C + (size_t)(r + 8) * 512 + col) =
                make_float2(acc[mt][nt][2] + bb0, acc[mt][nt][3] + bb1);
        }
    }
}

// ---------------------------------------------------------------------------
// Flash attention (causal), tf32 mma, cp.async double-buffered KV.
// Block: 4 warps, 64 q-rows (16/warp), KV tile = 64 keys, 2 stages.
//   sK,sV raw fp32 [2][64][76]; frag banks: K 12g+t, V 12t+g (conflict-free)
//   sP tf32 [64][72], per-warp private.
// One __syncthreads per tile; prefetch overlaps full tile compute.
// ---------------------------------------------------------------------------
#define KVST 76
#define KVSZ (64 * KVST)     // floats per tile
#define PST2 72

__global__ __launch_bounds__(128, 2)
void attn_tf32_kernel()
{
    extern __shared__ __align__(16) float asmem[];
    float* sK = asmem;                       // [2][KVSZ]
    float* sV = asmem + 2 * KVSZ;            // [2][KVSZ]
    unsigned* sP = (unsigned*)(asmem + 4 * KVSZ);   // [64*72]

    const int tid  = threadIdx.x;
    const int lane = tid & 31;
    const int w    = tid >> 5;
    const int g    = lane >> 2;
    const int t    = lane & 3;

    const int qt  = gridDim.x - 1 - blockIdx.x;  // heavy tiles first
    const int q0  = qt * 64;
    const int b   = blockIdx.y >> 3;
    const int h   = blockIdx.y & 7;
    const int wq  = w * 16;

    const float* kbase = g_k + (size_t)(b * S_) * 512 + h * 64;
    const float* vbase = g_v + (size_t)(b * S_) * 512 + h * 64;

    auto prefetch_kv = [&](int st, int j0) {
        const float* kp = kbase + (size_t)j0 * 512;
        const float* vp = vbase + (size_t)j0 * 512;
        float* dk = sK + st * KVSZ;
        float* dv = sV + st * KVSZ;
#pragma unroll
        for (int i = 0; i < 8; i++) {
            int ch = tid + i * 128;      // 0..1023
            int r  = ch >> 4;            // key row
            int cc = (ch & 15) * 4;      // float col of 16B chunk
            cpa16(dk + r * KVST + cc, kp + (size_t)r * 512 + cc);
            cpa16(dv + r * KVST + cc, vp + (size_t)r * 512 + cc);
        }
    };

    // Q fragments (scale 0.125 folded in), register resident
    unsigned qf[8][4];
    {
        const float* qp = g_q + (size_t)(b * S_ + q0 + wq) * 512 + h * 64;
#pragma unroll
        for (int c = 0; c < 8; c++) {
            qf[c][0] = f2tf(0.125f * qp[(size_t)g * 512 + c * 8 + t]);
            qf[c][1] = f2tf(0.125f * qp[(size_t)(g + 8) * 512 + c * 8 + t]);
            qf[c][2] = f2tf(0.125f * qp[(size_t)g * 512 + c * 8 + t + 4]);
            qf[c][3] = f2tf(0.125f * qp[(size_t)(g + 8) * 512 + c * 8 + t + 4]);
        }
    }

    float o[8][4];
#pragma unroll
    for (int nt = 0; nt < 8; nt++)
#pragma unroll
        for (int i = 0; i < 4; i++) o[nt][i] = 0.f;
    float m0 = -1e30f, m1 = -1e30f, l0 = 0.f, l1 = 0.f;

    const int p0slot = (t & 1) * 4 + (t >> 1);
    const int jend = q0 + 64;

    prefetch_kv(0, 0);
    CP_COMMIT();

    for (int j0 = 0; j0 < jend; j0 += 64) {
        const int st = (j0 >> 6) & 1;
        CP_WAIT0();
        __syncthreads();           // tile st ready; all warps done with st^1
        if (j0 + 64 < jend) prefetch_kv(st ^ 1, j0 + 64);
        CP_COMMIT();

        if (j0 > q0 + wq + 15) continue;   // tile fully above this warp's rows

        const float* sKst = sK + st * KVSZ;
        const float* sVst = sV + st * KVSZ;

        // ---- S = Q @ K^T (16 rows x 64 keys) ----
        float s[8][4];
#pragma unroll
        for (int nt = 0; nt < 8; nt++)
#pragma unroll
            for (int i = 0; i < 4; i++) s[nt][i] = 0.f;
#pragma unroll
        for (int c = 0; c < 8; c++)
#pragma unroll
            for (int nt = 0; nt < 8; nt++) {
                const float* kr = sKst + (nt * 8 + g) * KVST + c * 8;
                unsigned bf[2] = { f2tf(kr[t]), f2tf(kr[t + 4]) };
                mma_tf32(s[nt], qf[c], bf);
            }

        // ---- causal mask (diagonal-overlapping tiles only) ----
        if (j0 + 63 > q0 + wq) {
            int r0 = q0 + wq + g;
#pragma unroll
            for (int nt = 0; nt < 8; nt++) {
                int c0 = j0 + nt * 8 + t * 2;
                if (c0     > r0)     s[nt][0] = -1e30f;
                if (c0 + 1 > r0)     s[nt][1] = -1e30f;
                if (c0     > r0 + 8) s[nt][2] = -1e30f;
                if (c0 + 1 > r0 + 8) s[nt][3] = -1e30f;
            }
        }

        // ---- online softmax ----
        float mx0 = -1e30f, mx1 = -1e30f;
#pragma unroll
        for (int nt = 0; nt < 8; nt++) {
            mx0 = fmaxf(mx0, fmaxf(s[nt][0], s[nt][1]));
            mx1 = fmaxf(mx1, fmaxf(s[nt][2], s[nt][3]));
        }
        mx0 = fmaxf(mx0, __shfl_xor_sync(0xffffffffu, mx0, 1));
        mx0 = fmaxf(mx0, __shfl_xor_sync(0xffffffffu, mx0, 2));
        mx1 = fmaxf(mx1, __shfl_xor_sync(0xffffffffu, mx1, 1));
        mx1 = fmaxf(mx1, __shfl_xor_sync(0xffffffffu, mx1, 2));
        float nm0 = fmaxf(m0, mx0), nm1 = fmaxf(m1, mx1);
        float cor0 = __expf(m0 - nm0), cor1 = __expf(m1 - nm1);
        m0 = nm0; m1 = nm1;

        float ls0 = 0.f, ls1 = 0.f;
        {
            int rowA = (wq + g) * PST2;
            int rowB = rowA + 8 * PST2;
#pragma unroll
            for (int nt = 0; nt < 8; nt++) {
                float e0 = __expf(s[nt][0] - nm0);
                float e1 = __expf(s[nt][1] - nm0);
                float e2 = __expf(s[nt][2] - nm1);
                float e3 = __expf(s[nt][3] - nm1);
                ls0 += e0 + e1; ls1 += e2 + e3;
                sP[rowA + nt * 8 + p0slot]     = f2tf(e0);
                sP[rowA + nt * 8 + p0slot + 2] = f2tf(e1);
                sP[rowB + nt * 8 + p0slot]     = f2tf(e2);
                sP[rowB + nt * 8 + p0slot + 2] = f2tf(e3);
            }
        }
        ls0 += __shfl_xor_sync(0xffffffffu, ls0, 1);
        ls0 += __shfl_xor_sync(0xffffffffu, ls0, 2);
        ls1 += __shfl_xor_sync(0xffffffffu, ls1, 1);
        ls1 += __shfl_xor_sync(0xffffffffu, ls1, 2);
        l0 = l0 * cor0 + ls0;
        l1 = l1 * cor1 + ls1;

#pragma unroll
        for (int nt = 0; nt < 8; nt++) {
            o[nt][0] *= cor0; o[nt][1] *= cor0;
            o[nt][2] *= cor1; o[nt][3] *= cor1;
        }
        __syncwarp();   // P visible across this warp

        // ---- O += P @ V ----
#pragma unroll
        for (int c = 0; c < 8; c++) {
            unsigned pa[4];
            uint2 lo = *(const uint2*)&sP[(wq + g) * PST2 + c * 8 + t * 2];
            uint2 hi = *(const uint2*)&sP[(wq + g + 8) * PST2 + c * 8 + t * 2];
            pa[0] = lo.x; pa[2] = lo.y;
            pa[1] = hi.x; pa[3] = hi.y;
#pragma unroll
            for (int nt = 0; nt < 8; nt++) {
                unsigned bf[2];
                bf[0] = f2tf(sVst[(c * 8 + t) * KVST + nt * 8 + g]);
                bf[1] = f2tf(sVst[(c * 8 + t + 4) * KVST + nt * 8 + g]);
                mma_tf32(o[nt], pa, bf);
            }
        }
    }

    // ---- normalize + store (concat layout [B*S, H*64]) ----
    float inv0 = 1.f / l0, inv1 = 1.f / l1;
    float* op = g_ctx + (size_t)(b * S_ + q0 + wq) * 512 + h * 64;
#pragma unroll
    for (int nt = 0; nt < 8; nt++) {
        int col = nt * 8 + t * 2;
        *(float2*)(op + (size_t)g * 512 + col) =
            make_float2(o[nt][0] * inv0, o[nt][1] * inv0);
        *(float2*)(op + (size_t)(g + 8) * 512 + col) =
            make_float2(o[nt][2] * inv1, o[nt][3] * inv1);
    }
}

#define ATTN_SMEM ((4 * KVSZ) * 4 + 64 * PST2 * 4)   // 77824 + 18432 = 96256 B

// ---------------------------------------------------------------------------
// Launch.  inputs: 0 Q,1 K,2 V,3 mask(all-true),4 Wq,5 bq,6 Wk,7 bk,
//                  8 Wv,9 bv,10 Wo,11 bo
// ---------------------------------------------------------------------------
extern "C" void kernel_launch(void* const* d_in, const int* in_sizes, int n_in,
                              void* d_out, int out_size)
{
    const float* Q  = (const float*)d_in[0];
    const float* K  = (const float*)d_in[1];
    const float* V  = (const float*)d_in[2];
    const float* Wq = (const float*)d_in[4];
    const float* bq = (const float*)d_in[5];
    const float* Wk = (const float*)d_in[6];
    const float* bk = (const float*)d_in[7];
    const float* Wv = (const float*)d_in[8];
    const float* bv = (const float*)d_in[9];
    const float* Wo = (const float*)d_in[10];
    const float* bo = (const float*)d_in[11];
    float* out = (float*)d_out;

    static int inited = 0;
    if (!inited) {
        cudaFuncSetAttribute(attn_tf32_kernel,
                             cudaFuncAttributeMaxDynamicSharedMemorySize, ATTN_SMEM);
        inited = 1;
    }

    // QKV projections in one launch (z selects Q/K/V)
    dim3 gq(M_ / GBM, NW_ / GBN, 3);   // 64 x 4 x 3
    gemm_tf32_kernel<true><<<gq, 256>>>(Q, K, V, Wq, Wk, Wv, bq, bk, bv, nullptr);

    // Causal attention
    dim3 ga(S_ / 64, B_ * H_);         // 32 x 32
    attn_tf32_kernel<<<ga, 128, ATTN_SMEM>>>();

    // Output projection
    dim3 gg(M_ / GBM, NW_ / GBN);      // 64 x 4
    gemm_tf32_kernel<false><<<gg, 256>>>(nullptr, nullptr, nullptr,
                                         Wo, nullptr, nullptr,
                                         bo, nullptr, nullptr, out);
}

// round 9
// speedup vs baseline: 1.2605x; 1.0339x over previous
#include <cuda_runtime.h>
#include <cstdint>

// Problem constants
#define B_  4
#define S_  2048
#define D_  512
#define H_  8
#define HD_ 64
#define M_  (B_*S_)       // 8192
#define NW_ 512

// Scratch (device globals)
__device__ float g_q[M_ * NW_];
__device__ float g_k[M_ * NW_];
__device__ float g_v[M_ * NW_];
__device__ float g_ctx[M_ * NW_];
// tf32-rounded weight copies
__device__ float g_wq2[H_ * D_ * HD_];
__device__ float g_wk2[H_ * D_ * HD_];
__device__ float g_wv2[H_ * D_ * HD_];
__device__ float g_wo2[D_ * NW_];

__device__ __forceinline__ unsigned f2tf(float f) {
    unsigned u;
    asm("cvt.rna.tf32.f32 %0, %1;" : "=r"(u) : "f"(f));
    return u;
}
__device__ __forceinline__ float tf32f(float f) {
    return __uint_as_float(f2tf(f));
}

__device__ __forceinline__ void mma_tf32(float* c, const unsigned* a, const unsigned* b) {
    asm volatile("mma.sync.aligned.m16n8k8.row.col.f32.tf32.tf32.f32 "
        "{%0,%1,%2,%3}, {%4,%5,%6,%7}, {%8,%9}, {%0,%1,%2,%3};"
        : "+f"(c[0]), "+f"(c[1]), "+f"(c[2]), "+f"(c[3])
        : "r"(a[0]), "r"(a[1]), "r"(a[2]), "r"(a[3]), "r"(b[0]), "r"(b[1]));
}

__device__ __forceinline__ void cpa16(void* sptr, const void* g) {
    unsigned sa = (unsigned)__cvta_generic_to_shared(sptr);
    asm volatile("cp.async.cg.shared.global [%0], [%1], 16;" :: "r"(sa), "l"(g));
}
#define CP_COMMIT() asm volatile("cp.async.commit_group;" ::: "memory")
#define CP_WAIT0()  asm volatile("cp.async.wait_group 0;" ::: "memory")

// ---------------------------------------------------------------------------
// Prep: round the four weight matrices to tf32 once (elementwise, ~2us).
// ---------------------------------------------------------------------------
__global__ __launch_bounds__(256)
void prep_weights_kernel(const float* __restrict__ wq,
                         const float* __restrict__ wk,
                         const float* __restrict__ wv,
                         const float* __restrict__ wo)
{
    int i = blockIdx.x * 256 + threadIdx.x;   // grid covers 262144
    g_wq2[i] = tf32f(wq[i]);
    g_wk2[i] = tf32f(wk[i]);
    g_wv2[i] = tf32f(wv[i]);
    g_wo2[i] = tf32f(wo[i]);
}

// ---------------------------------------------------------------------------
// tf32 GEMM, cp.async double-buffered (round-6 structure).
// C[8192,512] = A[8192,512] @ W(512,512) + bias[512]
// QKV=true : A = raw inputs (cvt A-frags at use), W = g_w?2 (pre-rounded, raw),
//            C stored tf32-rounded.
// QKV=false: A = g_ctx (pre-rounded, raw), W = g_wo2 (raw), C stored full fp32.
// Block 128x128x16, 256 threads, 8 warps (2m x 4n), warp tile 64x32.
// ---------------------------------------------------------------------------
#define GBM 128
#define GBN 128
#define GBK 16
#define ASTR 20
#define BSTR 136

template<bool QKV>
__global__ __launch_bounds__(256, 2)
void gemm_tf32_kernel(const float* __restrict__ A0,
                      const float* __restrict__ A1,
                      const float* __restrict__ A2,
                      const float* __restrict__ b0p,
                      const float* __restrict__ b1p,
                      const float* __restrict__ b2p,
                      float* __restrict__ Cout)
{
    const float* A; const float* W; const float* bias; float* C;
    if (QKV) {
        int z = blockIdx.z;
        A    = (z == 0) ? A0 : (z == 1) ? A1 : A2;
        W    = (z == 0) ? g_wq2 : (z == 1) ? g_wk2 : g_wv2;
        bias = (z == 0) ? b0p : (z == 1) ? b1p : b2p;
        C    = (z == 0) ? g_q : (z == 1) ? g_k : g_v;
    } else {
        A = g_ctx; W = g_wo2; bias = b0p; C = Cout;
    }

    __shared__ __align__(16) float As[2][GBM * ASTR];
    __shared__ __align__(16) float Bs[2][GBK * BSTR];

    const int tid  = threadIdx.x;
    const int lane = tid & 31;
    const int w    = tid >> 5;
    const int g    = lane >> 2;
    const int t    = lane & 3;

    const int bm0 = blockIdx.x * GBM;
    const int bn0 = blockIdx.y * GBN;
    const int wm0 = (w & 1) * 64;
    const int wn0 = (w >> 1) * 32;

    const int aRow = tid >> 1;
    const int aK   = (tid & 1) * 8;
    const int bR   = tid >> 4;
    const int bN   = (tid & 15) * 4;

    float acc[4][4][4];
#pragma unroll
    for (int mt = 0; mt < 4; mt++)
#pragma unroll
        for (int nt = 0; nt < 4; nt++)
#pragma unroll
            for (int i = 0; i < 4; i++) acc[mt][nt][i] = 0.f;

    auto prefetch = [&](int st, int k0) {
        const float* ap = A + (size_t)(bm0 + aRow) * 512 + k0 + aK;
        cpa16(&As[st][aRow * ASTR + aK], ap);
        cpa16(&As[st][aRow * ASTR + aK + 4], ap + 4);
#pragma unroll
        for (int j = 0; j < 2; j++) {
            int n = bn0 + bN + j * 64;
            const float* bp;
            if (QKV) bp = W + (size_t)(n >> 6) * (D_ * 64) + (size_t)(k0 + bR) * 64 + (n & 63);
            else     bp = W + (size_t)(k0 + bR) * 512 + n;
            cpa16(&Bs[st][bR * BSTR + bN + j * 64], bp);
        }
    };

    prefetch(0, 0);
    CP_COMMIT();

    for (int it = 0; it < 32; it++) {
        const int st = it & 1;
        CP_WAIT0();
        __syncthreads();
        if (it + 1 < 32) prefetch(st ^ 1, (it + 1) * GBK);
        CP_COMMIT();

        const unsigned* Bsu = (const unsigned*)Bs[st];

#pragma unroll
        for (int kc = 0; kc < 16; kc += 8) {
            unsigned af[4][4], bf[4][2];
#pragma unroll
            for (int mt = 0; mt < 4; mt++) {
                int r = wm0 + mt * 16 + g;
                const float* ar  = &As[st][r * ASTR + kc + t];
                const float* ar8 = ar + 8 * ASTR;
                if (QKV) {
                    af[mt][0] = f2tf(ar[0]);
                    af[mt][2] = f2tf(ar[4]);
                    af[mt][1] = f2tf(ar8[0]);
                    af[mt][3] = f2tf(ar8[4]);
                } else {   // A = g_ctx, pre-rounded to tf32
                    af[mt][0] = __float_as_uint(ar[0]);
                    af[mt][2] = __float_as_uint(ar[4]);
                    af[mt][1] = __float_as_uint(ar8[0]);
                    af[mt][3] = __float_as_uint(ar8[4]);
                }
            }
#pragma unroll
            for (int nt = 0; nt < 4; nt++) {   // W pre-rounded -> raw bits
                int cn = wn0 + nt * 8 + g;
                bf[nt][0] = Bsu[(kc + t) * BSTR + cn];
                bf[nt][1] = Bsu[(kc + t + 4) * BSTR + cn];
            }
#pragma unroll
            for (int mt = 0; mt < 4; mt++)
#pragma unroll
                for (int nt = 0; nt < 4; nt++)
                    mma_tf32(acc[mt][nt], af[mt], bf[nt]);
        }
    }

#pragma unroll
    for (int mt = 0; mt < 4; mt++) {
        int r = bm0 + wm0 + mt * 16 + g;
#pragma unroll
        for (int nt = 0; nt < 4; nt++) {
            int col = bn0 + wn0 + nt * 8 + t * 2;
            float bb0 = bias[col], bb1 = bias[col + 1];
            float c0 = acc[mt][nt][0] + bb0, c1 = acc[mt][nt][1] + bb1;
            float c2 = acc[mt][nt][2] + bb0, c3 = acc[mt][nt][3] + bb1;
            if (QKV) {   // q/k/v consumed as tf32 downstream -> round at store
                c0 = tf32f(c0); c1 = tf32f(c1); c2 = tf32f(c2); c3 = tf32f(c3);
            }
            *(float2*)(C + (size_t)r * 512 + col)       = make_float2(c0, c1);
            *(float2*)(C + (size_t)(r + 8) * 512 + col) = make_float2(c2, c3);
        }
    }
}

// ---------------------------------------------------------------------------
// Flash attention (causal), tf32 mma, cp.async double-buffered KV.
// EXACT round-6 structure (passing): 4 warps, 64 q-rows, 64-key tiles,
// KVST 76, separate sP (PST2 72), one __syncthreads per tile.
// Only change: K/V/Q are pre-rounded tf32 -> fragments use raw bits.
// ---------------------------------------------------------------------------
#define KVST 76
#define KVSZ (64 * KVST)
#define PST2 72

__global__ __launch_bounds__(128, 2)
void attn_tf32_kernel()
{
    extern __shared__ __align__(16) float asmem[];
    float* sK = asmem;                       // [2][KVSZ]
    float* sV = asmem + 2 * KVSZ;            // [2][KVSZ]
    unsigned* sP = (unsigned*)(asmem + 4 * KVSZ);   // [64*72]

    const int tid  = threadIdx.x;
    const int lane = tid & 31;
    const int w    = tid >> 5;
    const int g    = lane >> 2;
    const int t    = lane & 3;

    const int qt  = gridDim.x - 1 - blockIdx.x;  // heavy tiles first
    const int q0  = qt * 64;
    const int b   = blockIdx.y >> 3;
    const int h   = blockIdx.y & 7;
    const int wq  = w * 16;

    const float* kbase = g_k + (size_t)(b * S_) * 512 + h * 64;
    const float* vbase = g_v + (size_t)(b * S_) * 512 + h * 64;

    auto prefetch_kv = [&](int st, int j0) {
        const float* kp = kbase + (size_t)j0 * 512;
        const float* vp = vbase + (size_t)j0 * 512;
        float* dk = sK + st * KVSZ;
        float* dv = sV + st * KVSZ;
#pragma unroll
        for (int i = 0; i < 8; i++) {
            int ch = tid + i * 128;      // 0..1023
            int r  = ch >> 4;            // key row
            int cc = (ch & 15) * 4;      // float col of 16B chunk
            cpa16(dk + r * KVST + cc, kp + (size_t)r * 512 + cc);
            cpa16(dv + r * KVST + cc, vp + (size_t)r * 512 + cc);
        }
    };

    // Q fragments: g_q pre-rounded tf32; *0.125 is exact -> raw bits
    unsigned qf[8][4];
    {
        const float* qp = g_q + (size_t)(b * S_ + q0 + wq) * 512 + h * 64;
#pragma unroll
        for (int c = 0; c < 8; c++) {
            qf[c][0] = __float_as_uint(0.125f * qp[(size_t)g * 512 + c * 8 + t]);
            qf[c][1] = __float_as_uint(0.125f * qp[(size_t)(g + 8) * 512 + c * 8 + t]);
            qf[c][2] = __float_as_uint(0.125f * qp[(size_t)g * 512 + c * 8 + t + 4]);
            qf[c][3] = __float_as_uint(0.125f * qp[(size_t)(g + 8) * 512 + c * 8 + t + 4]);
        }
    }

    float o[8][4];
#pragma unroll
    for (int nt = 0; nt < 8; nt++)
#pragma unroll
        for (int i = 0; i < 4; i++) o[nt][i] = 0.f;
    float m0 = -1e30f, m1 = -1e30f, l0 = 0.f, l1 = 0.f;

    const int p0slot = (t & 1) * 4 + (t >> 1);
    const int jend = q0 + 64;

    prefetch_kv(0, 0);
    CP_COMMIT();

    for (int j0 = 0; j0 < jend; j0 += 64) {
        const int st = (j0 >> 6) & 1;
        CP_WAIT0();
        __syncthreads();           // tile st ready; all warps done with st^1
        if (j0 + 64 < jend) prefetch_kv(st ^ 1, j0 + 64);
        CP_COMMIT();

        if (j0 > q0 + wq + 15) continue;   // tile fully above this warp's rows

        const unsigned* sKst = (const unsigned*)(sK + st * KVSZ);
        const unsigned* sVst = (const unsigned*)(sV + st * KVSZ);

        // ---- S = Q @ K^T (16 rows x 64 keys) ----
        float s[8][4];
#pragma unroll
        for (int nt = 0; nt < 8; nt++)
#pragma unroll
            for (int i = 0; i < 4; i++) s[nt][i] = 0.f;
#pragma unroll
        for (int c = 0; c < 8; c++)
#pragma unroll
            for (int nt = 0; nt < 8; nt++) {
                const unsigned* kr = sKst + (nt * 8 + g) * KVST + c * 8;
                unsigned bf[2] = { kr[t], kr[t + 4] };   // pre-rounded tf32
                mma_tf32(s[nt], qf[c], bf);
            }

        // ---- causal mask (diagonal-overlapping tiles only) ----
        if (j0 + 63 > q0 + wq) {
            int r0 = q0 + wq + g;
#pragma unroll
            for (int nt = 0; nt < 8; nt++) {
                int c0 = j0 + nt * 8 + t * 2;
                if (c0     > r0)     s[nt][0] = -1e30f;
                if (c0 + 1 > r0)     s[nt][1] = -1e30f;
                if (c0     > r0 + 8) s[nt][2] = -1e30f;
                if (c0 + 1 > r0 + 8) s[nt][3] = -1e30f;
            }
        }

        // ---- online softmax ----
        float mx0 = -1e30f, mx1 = -1e30f;
#pragma unroll
        for (int nt = 0; nt < 8; nt++) {
            mx0 = fmaxf(mx0, fmaxf(s[nt][0], s[nt][1]));
            mx1 = fmaxf(mx1, fmaxf(s[nt][2], s[nt][3]));
        }
        mx0 = fmaxf(mx0, __shfl_xor_sync(0xffffffffu, mx0, 1));
        mx0 = fmaxf(mx0, __shfl_xor_sync(0xffffffffu, mx0, 2));
        mx1 = fmaxf(mx1, __shfl_xor_sync(0xffffffffu, mx1, 1));
        mx1 = fmaxf(mx1, __shfl_xor_sync(0xffffffffu, mx1, 2));
        float nm0 = fmaxf(m0, mx0), nm1 = fmaxf(m1, mx1);
        float cor0 = __expf(m0 - nm0), cor1 = __expf(m1 - nm1);
        m0 = nm0; m1 = nm1;

        float ls0 = 0.f, ls1 = 0.f;
        {
            int rowA = (wq + g) * PST2;
            int rowB = rowA + 8 * PST2;
#pragma unroll
            for (int nt = 0; nt < 8; nt++) {
                float e0 = __expf(s[nt][0] - nm0);
                float e1 = __expf(s[nt][1] - nm0);
                float e2 = __expf(s[nt][2] - nm1);
                float e3 = __expf(s[nt][3] - nm1);
                ls0 += e0 + e1; ls1 += e2 + e3;
                sP[rowA + nt * 8 + p0slot]     = f2tf(e0);
                sP[rowA + nt * 8 + p0slot + 2] = f2tf(e1);
                sP[rowB + nt * 8 + p0slot]     = f2tf(e2);
                sP[rowB + nt * 8 + p0slot + 2] = f2tf(e3);
            }
        }
        ls0 += __shfl_xor_sync(0xffffffffu, ls0, 1);
        ls0 += __shfl_xor_sync(0xffffffffu, ls0, 2);
        ls1 += __shfl_xor_sync(0xffffffffu, ls1, 1);
        ls1 += __shfl_xor_sync(0xffffffffu, ls1, 2);
        l0 = l0 * cor0 + ls0;
        l1 = l1 * cor1 + ls1;

#pragma unroll
        for (int nt = 0; nt < 8; nt++) {
            o[nt][0] *= cor0; o[nt][1] *= cor0;
            o[nt][2] *= cor1; o[nt][3] *= cor1;
        }
        __syncwarp();   // P visible across this warp (rows are warp-private)

        // ---- O += P @ V ----
#pragma unroll
        for (int c = 0; c < 8; c++) {
            unsigned pa[4];
            uint2 lo = *(const uint2*)&sP[(wq + g) * PST2 + c * 8 + t * 2];
            uint2 hi = *(const uint2*)&sP[(wq + g + 8) * PST2 + c * 8 + t * 2];
            pa[0] = lo.x; pa[2] = lo.y;
            pa[1] = hi.x; pa[3] = hi.y;
#pragma unroll
            for (int nt = 0; nt < 8; nt++) {
                unsigned bf[2];                       // pre-rounded tf32
                bf[0] = sVst[(c * 8 + t) * KVST + nt * 8 + g];
                bf[1] = sVst[(c * 8 + t + 4) * KVST + nt * 8 + g];
                mma_tf32(o[nt], pa, bf);
            }
        }
    }

    // ---- normalize + store, tf32-rounded (consumed as tf32 by out-proj) ----
    float inv0 = 1.f / l0, inv1 = 1.f / l1;
    float* op = g_ctx + (size_t)(b * S_ + q0 + wq) * 512 + h * 64;
#pragma unroll
    for (int nt = 0; nt < 8; nt++) {
        int col = nt * 8 + t * 2;
        *(float2*)(op + (size_t)g * 512 + col) =
            make_float2(tf32f(o[nt][0] * inv0), tf32f(o[nt][1] * inv0));
        *(float2*)(op + (size_t)(g + 8) * 512 + col) =
            make_float2(tf32f(o[nt][2] * inv1), tf32f(o[nt][3] * inv1));
    }
}

#define ATTN_SMEM (4 * KVSZ * 4 + 64 * PST2 * 4)   // 77824 + 18432 = 96256 B

// ---------------------------------------------------------------------------
// Launch.  inputs: 0 Q,1 K,2 V,3 mask(all-true),4 Wq,5 bq,6 Wk,7 bk,
//                  8 Wv,9 bv,10 Wo,11 bo
// ---------------------------------------------------------------------------
extern "C" void kernel_launch(void* const* d_in, const int* in_sizes, int n_in,
                              void* d_out, int out_size)
{
    const float* Q  = (const float*)d_in[0];
    const float* K  = (const float*)d_in[1];
    const float* V  = (const float*)d_in[2];
    const float* Wq = (const float*)d_in[4];
    const float* bq = (const float*)d_in[5];
    const float* Wk = (const float*)d_in[6];
    const float* bk = (const float*)d_in[7];
    const float* Wv = (const float*)d_in[8];
    const float* bv = (const float*)d_in[9];
    const float* Wo = (const float*)d_in[10];
    const float* bo = (const float*)d_in[11];
    float* out = (float*)d_out;

    cudaFuncSetAttribute(attn_tf32_kernel,
                         cudaFuncAttributeMaxDynamicSharedMemorySize, ATTN_SMEM);

    // Round weights to tf32 once per launch
    prep_weights_kernel<<<(H_ * D_ * HD_) / 256, 256>>>(Wq, Wk, Wv, Wo);

    // QKV projections in one launch (z selects Q/K/V)
    dim3 gq(M_ / GBM, NW_ / GBN, 3);   // 64 x 4 x 3
    gemm_tf32_kernel<true><<<gq, 256>>>(Q, K, V, bq, bk, bv, nullptr);

    // Causal attention
    dim3 ga(S_ / 64, B_ * H_);         // 32 x 32
    attn_tf32_kernel<<<ga, 128, ATTN_SMEM>>>();

    // Output projection
    dim3 gg(M_ / GBM, NW_ / GBN);      // 64 x 4
    gemm_tf32_kernel<false><<<gg, 256>>>(nullptr, nullptr, nullptr,
                                         bo, nullptr, nullptr, out);
}

// round 10
// speedup vs baseline: 1.3038x; 1.0344x over previous
#include <cuda_runtime.h>
#include <cstdint>

// Problem constants
#define B_  4
#define S_  2048
#define D_  512
#define H_  8
#define HD_ 64
#define M_  (B_*S_)       // 8192
#define NW_ 512

// Scratch (device globals)
__device__ float g_q[M_ * NW_];
__device__ float g_k[M_ * NW_];
__device__ float g_v[M_ * NW_];
__device__ float g_ctx[M_ * NW_];
// tf32-rounded weight copies
__device__ float g_wq2[H_ * D_ * HD_];
__device__ float g_wk2[H_ * D_ * HD_];
__device__ float g_wv2[H_ * D_ * HD_];
__device__ float g_wo2[D_ * NW_];

__device__ __forceinline__ unsigned f2tf(float f) {
    unsigned u;
    asm("cvt.rna.tf32.f32 %0, %1;" : "=r"(u) : "f"(f));
    return u;
}
__device__ __forceinline__ float tf32f(float f) {
    return __uint_as_float(f2tf(f));
}

__device__ __forceinline__ void mma_tf32(float* c, const unsigned* a, const unsigned* b) {
    asm volatile("mma.sync.aligned.m16n8k8.row.col.f32.tf32.tf32.f32 "
        "{%0,%1,%2,%3}, {%4,%5,%6,%7}, {%8,%9}, {%0,%1,%2,%3};"
        : "+f"(c[0]), "+f"(c[1]), "+f"(c[2]), "+f"(c[3])
        : "r"(a[0]), "r"(a[1]), "r"(a[2]), "r"(a[3]), "r"(b[0]), "r"(b[1]));
}

__device__ __forceinline__ void cpa16(void* sptr, const void* g) {
    unsigned sa = (unsigned)__cvta_generic_to_shared(sptr);
    asm volatile("cp.async.cg.shared.global [%0], [%1], 16;" :: "r"(sa), "l"(g));
}
#define CP_COMMIT() asm volatile("cp.async.commit_group;" ::: "memory")
#define CP_WAIT0()  asm volatile("cp.async.wait_group 0;" ::: "memory")
#define CP_WAIT1()  asm volatile("cp.async.wait_group 1;" ::: "memory")

// ---------------------------------------------------------------------------
// Prep: round the four weight matrices to tf32 once.
// ---------------------------------------------------------------------------
__global__ __launch_bounds__(256)
void prep_weights_kernel(const float* __restrict__ wq,
                         const float* __restrict__ wk,
                         const float* __restrict__ wv,
                         const float* __restrict__ wo)
{
    int i = blockIdx.x * 256 + threadIdx.x;
    g_wq2[i] = tf32f(wq[i]);
    g_wk2[i] = tf32f(wk[i]);
    g_wv2[i] = tf32f(wv[i]);
    g_wo2[i] = tf32f(wo[i]);
}

// ---------------------------------------------------------------------------
// tf32 GEMM, cp.async 3-stage pipeline (wait_group 1).
// C[8192,512] = A[8192,512] @ W(512,512) + bias[512]
// QKV=true : A = raw inputs (cvt at frag build), W pre-rounded, C tf32-rounded.
// QKV=false: A = g_ctx (pre-rounded), W = g_wo2, C full fp32.
// Block 128x128x16, 256 threads, 8 warps (2m x 4n), warp tile 64x32.
// Dynamic smem: 3 * (128*20 + 16*136) * 4 = 56832 B.
// ---------------------------------------------------------------------------
#define GBM 128
#define GBN 128
#define GBK 16
#define ASTR 20
#define BSTR 136
#define GEMM_SMEM (3 * (GBM * ASTR + GBK * BSTR) * 4)

template<bool QKV>
__global__ __launch_bounds__(256, 2)
void gemm_tf32_kernel(const float* __restrict__ A0,
                      const float* __restrict__ A1,
                      const float* __restrict__ A2,
                      const float* __restrict__ b0p,
                      const float* __restrict__ b1p,
                      const float* __restrict__ b2p,
                      float* __restrict__ Cout)
{
    const float* A; const float* W; const float* bias; float* C;
    if (QKV) {
        int z = blockIdx.z;
        A    = (z == 0) ? A0 : (z == 1) ? A1 : A2;
        W    = (z == 0) ? g_wq2 : (z == 1) ? g_wk2 : g_wv2;
        bias = (z == 0) ? b0p : (z == 1) ? b1p : b2p;
        C    = (z == 0) ? g_q : (z == 1) ? g_k : g_v;
    } else {
        A = g_ctx; W = g_wo2; bias = b0p; C = Cout;
    }

    extern __shared__ __align__(16) float gsm[];
    float* As = gsm;                        // [3][GBM*ASTR]
    float* Bs = gsm + 3 * GBM * ASTR;       // [3][GBK*BSTR]

    const int tid  = threadIdx.x;
    const int lane = tid & 31;
    const int w    = tid >> 5;
    const int g    = lane >> 2;
    const int t    = lane & 3;

    const int bm0 = blockIdx.x * GBM;
    const int bn0 = blockIdx.y * GBN;
    const int wm0 = (w & 1) * 64;
    const int wn0 = (w >> 1) * 32;

    const int aRow = tid >> 1;
    const int aK   = (tid & 1) * 8;
    const int bR   = tid >> 4;
    const int bN   = (tid & 15) * 4;

    float acc[4][4][4];
#pragma unroll
    for (int mt = 0; mt < 4; mt++)
#pragma unroll
        for (int nt = 0; nt < 4; nt++)
#pragma unroll
            for (int i = 0; i < 4; i++) acc[mt][nt][i] = 0.f;

    auto prefetch = [&](int st, int k0) {
        float* as = As + st * GBM * ASTR;
        float* bs = Bs + st * GBK * BSTR;
        const float* ap = A + (size_t)(bm0 + aRow) * 512 + k0 + aK;
        cpa16(as + aRow * ASTR + aK, ap);
        cpa16(as + aRow * ASTR + aK + 4, ap + 4);
#pragma unroll
        for (int j = 0; j < 2; j++) {
            int n = bn0 + bN + j * 64;
            const float* bp;
            if (QKV) bp = W + (size_t)(n >> 6) * (D_ * 64) + (size_t)(k0 + bR) * 64 + (n & 63);
            else     bp = W + (size_t)(k0 + bR) * 512 + n;
            cpa16(bs + bR * BSTR + bN + j * 64, bp);
        }
    };

    prefetch(0, 0);
    CP_COMMIT();
    prefetch(1, GBK);
    CP_COMMIT();

    for (int it = 0; it < 32; it++) {
        const int st = it % 3;
        CP_WAIT1();                 // stage st landed (≤1 group pending)
        __syncthreads();
        if (it + 2 < 32) prefetch((it + 2) % 3, (it + 2) * GBK);
        CP_COMMIT();

        const float*    Asf = As + st * GBM * ASTR;
        const unsigned* Bsu = (const unsigned*)(Bs + st * GBK * BSTR);

#pragma unroll
        for (int kc = 0; kc < 16; kc += 8) {
            unsigned af[4][4], bf[4][2];
#pragma unroll
            for (int mt = 0; mt < 4; mt++) {
                int r = wm0 + mt * 16 + g;
                const float* ar  = &Asf[r * ASTR + kc + t];
                const float* ar8 = ar + 8 * ASTR;
                if (QKV) {
                    af[mt][0] = f2tf(ar[0]);
                    af[mt][2] = f2tf(ar[4]);
                    af[mt][1] = f2tf(ar8[0]);
                    af[mt][3] = f2tf(ar8[4]);
                } else {   // pre-rounded
                    af[mt][0] = __float_as_uint(ar[0]);
                    af[mt][2] = __float_as_uint(ar[4]);
                    af[mt][1] = __float_as_uint(ar8[0]);
                    af[mt][3] = __float_as_uint(ar8[4]);
                }
            }
#pragma unroll
            for (int nt = 0; nt < 4; nt++) {   // W pre-rounded
                int cn = wn0 + nt * 8 + g;
                bf[nt][0] = Bsu[(kc + t) * BSTR + cn];
                bf[nt][1] = Bsu[(kc + t + 4) * BSTR + cn];
            }
#pragma unroll
            for (int mt = 0; mt < 4; mt++)
#pragma unroll
                for (int nt = 0; nt < 4; nt++)
                    mma_tf32(acc[mt][nt], af[mt], bf[nt]);
        }
    }

#pragma unroll
    for (int mt = 0; mt < 4; mt++) {
        int r = bm0 + wm0 + mt * 16 + g;
#pragma unroll
        for (int nt = 0; nt < 4; nt++) {
            int col = bn0 + wn0 + nt * 8 + t * 2;
            float bb0 = bias[col], bb1 = bias[col + 1];
            float c0 = acc[mt][nt][0] + bb0, c1 = acc[mt][nt][1] + bb1;
            float c2 = acc[mt][nt][2] + bb0, c3 = acc[mt][nt][3] + bb1;
            if (QKV) {
                c0 = tf32f(c0); c1 = tf32f(c1); c2 = tf32f(c2); c3 = tf32f(c3);
            }
            *(float2*)(C + (size_t)r * 512 + col)       = make_float2(c0, c1);
            *(float2*)(C + (size_t)(r + 8) * 512 + col) = make_float2(c2, c3);
        }
    }
}

// ---------------------------------------------------------------------------
// Flash attention (causal), tf32 mma, cp.async double-buffered KV.
// Round-9 structure, KV tile shrunk 64 -> 32 keys for 4 blocks/SM:
//   4 warps, 64 q-rows (16/warp), 2-stage KV, KVST 76
//   (K frags banks 12g+t, V frags banks 12t+g: both conflict-free)
//   sP separate [64][40], per-warp-private rows.
// smem = (2*2*32*76 + 64*40)*4 = 49152 B -> 4 blocks/SM; regs capped 128.
// ---------------------------------------------------------------------------
#define KVST 76
#define KVSZ (32 * KVST)
#define PST2 40

__global__ __launch_bounds__(128, 4)
void attn_tf32_kernel()
{
    extern __shared__ __align__(16) float asmem[];
    float* sK = asmem;                       // [2][KVSZ]
    float* sV = asmem + 2 * KVSZ;            // [2][KVSZ]
    unsigned* sP = (unsigned*)(asmem + 4 * KVSZ);   // [64*40]

    const int tid  = threadIdx.x;
    const int lane = tid & 31;
    const int w    = tid >> 5;
    const int g    = lane >> 2;
    const int t    = lane & 3;

    const int qt  = gridDim.x - 1 - blockIdx.x;  // heavy tiles first
    const int q0  = qt * 64;
    const int b   = blockIdx.y >> 3;
    const int h   = blockIdx.y & 7;
    const int wq  = w * 16;

    const float* kbase = g_k + (size_t)(b * S_) * 512 + h * 64;
    const float* vbase = g_v + (size_t)(b * S_) * 512 + h * 64;

    auto prefetch_kv = [&](int st, int j0) {
        const float* kp = kbase + (size_t)j0 * 512;
        const float* vp = vbase + (size_t)j0 * 512;
        float* dk = sK + st * KVSZ;
        float* dv = sV + st * KVSZ;
#pragma unroll
        for (int i = 0; i < 4; i++) {
            int ch = tid + i * 128;      // 0..511
            int r  = ch >> 4;            // key row 0..31
            int cc = (ch & 15) * 4;      // float col of 16B chunk
            cpa16(dk + r * KVST + cc, kp + (size_t)r * 512 + cc);
            cpa16(dv + r * KVST + cc, vp + (size_t)r * 512 + cc);
        }
    };

    // Q fragments: g_q pre-rounded tf32; *0.125 exact -> raw bits
    unsigned qf[8][4];
    {
        const float* qp = g_q + (size_t)(b * S_ + q0 + wq) * 512 + h * 64;
#pragma unroll
        for (int c = 0; c < 8; c++) {
            qf[c][0] = __float_as_uint(0.125f * qp[(size_t)g * 512 + c * 8 + t]);
            qf[c][1] = __float_as_uint(0.125f * qp[(size_t)(g + 8) * 512 + c * 8 + t]);
            qf[c][2] = __float_as_uint(0.125f * qp[(size_t)g * 512 + c * 8 + t + 4]);
            qf[c][3] = __float_as_uint(0.125f * qp[(size_t)(g + 8) * 512 + c * 8 + t + 4]);
        }
    }

    float o[8][4];
#pragma unroll
    for (int nt = 0; nt < 8; nt++)
#pragma unroll
        for (int i = 0; i < 4; i++) o[nt][i] = 0.f;
    float m0 = -1e30f, m1 = -1e30f, l0 = 0.f, l1 = 0.f;

    const int p0slot = (t & 1) * 4 + (t >> 1);
    const int jend = q0 + 64;

    prefetch_kv(0, 0);
    CP_COMMIT();

    for (int j0 = 0; j0 < jend; j0 += 32) {
        const int st = (j0 >> 5) & 1;
        CP_WAIT0();
        __syncthreads();           // tile st ready; all warps done with st^1
        if (j0 + 32 < jend) prefetch_kv(st ^ 1, j0 + 32);
        CP_COMMIT();

        if (j0 > q0 + wq + 15) continue;   // tile fully above this warp's rows

        const unsigned* sKst = (const unsigned*)(sK + st * KVSZ);
        const unsigned* sVst = (const unsigned*)(sV + st * KVSZ);

        // ---- S = Q @ K^T (16 rows x 32 keys) ----
        float s[4][4];
#pragma unroll
        for (int nt = 0; nt < 4; nt++)
#pragma unroll
            for (int i = 0; i < 4; i++) s[nt][i] = 0.f;
#pragma unroll
        for (int c = 0; c < 8; c++)
#pragma unroll
            for (int nt = 0; nt < 4; nt++) {
                const unsigned* kr = sKst + (nt * 8 + g) * KVST + c * 8;
                unsigned bf[2] = { kr[t], kr[t + 4] };   // pre-rounded tf32
                mma_tf32(s[nt], qf[c], bf);
            }

        // ---- causal mask (diagonal-overlapping tiles only) ----
        if (j0 + 31 > q0 + wq) {
            int r0 = q0 + wq + g;
#pragma unroll
            for (int nt = 0; nt < 4; nt++) {
                int c0 = j0 + nt * 8 + t * 2;
                if (c0     > r0)     s[nt][0] = -1e30f;
                if (c0 + 1 > r0)     s[nt][1] = -1e30f;
                if (c0     > r0 + 8) s[nt][2] = -1e30f;
                if (c0 + 1 > r0 + 8) s[nt][3] = -1e30f;
            }
        }

        // ---- online softmax ----
        float mx0 = -1e30f, mx1 = -1e30f;
#pragma unroll
        for (int nt = 0; nt < 4; nt++) {
            mx0 = fmaxf(mx0, fmaxf(s[nt][0], s[nt][1]));
            mx1 = fmaxf(mx1, fmaxf(s[nt][2], s[nt][3]));
        }
        mx0 = fmaxf(mx0, __shfl_xor_sync(0xffffffffu, mx0, 1));
        mx0 = fmaxf(mx0, __shfl_xor_sync(0xffffffffu, mx0, 2));
        mx1 = fmaxf(mx1, __shfl_xor_sync(0xffffffffu, mx1, 1));
        mx1 = fmaxf(mx1, __shfl_xor_sync(0xffffffffu, mx1, 2));
        float nm0 = fmaxf(m0, mx0), nm1 = fmaxf(m1, mx1);
        float cor0 = __expf(m0 - nm0), cor1 = __expf(m1 - nm1);
        m0 = nm0; m1 = nm1;

        float ls0 = 0.f, ls1 = 0.f;
        {
            int rowA = (wq + g) * PST2;
            int rowB = rowA + 8 * PST2;
#pragma unroll
            for (int nt = 0; nt < 4; nt++) {
                float e0 = __expf(s[nt][0] - nm0);
                float e1 = __expf(s[nt][1] - nm0);
                float e2 = __expf(s[nt][2] - nm1);
                float e3 = __expf(s[nt][3] - nm1);
                ls0 += e0 + e1; ls1 += e2 + e3;
                sP[rowA + nt * 8 + p0slot]     = f2tf(e0);
                sP[rowA + nt * 8 + p0slot + 2] = f2tf(e1);
                sP[rowB + nt * 8 + p0slot]     = f2tf(e2);
                sP[rowB + nt * 8 + p0slot + 2] = f2tf(e3);
            }
        }
        ls0 += __shfl_xor_sync(0xffffffffu, ls0, 1);
        ls0 += __shfl_xor_sync(0xffffffffu, ls0, 2);
        ls1 += __shfl_xor_sync(0xffffffffu, ls1, 1);
        ls1 += __shfl_xor_sync(0xffffffffu, ls1, 2);
        l0 = l0 * cor0 + ls0;
        l1 = l1 * cor1 + ls1;

#pragma unroll
        for (int nt = 0; nt < 8; nt++) {
            o[nt][0] *= cor0; o[nt][1] *= cor0;
            o[nt][2] *= cor1; o[nt][3] *= cor1;
        }
        __syncwarp();   // P visible across this warp (rows are warp-private)

        // ---- O += P @ V ----
#pragma unroll
        for (int c = 0; c < 4; c++) {
            unsigned pa[4];
            uint2 lo = *(const uint2*)&sP[(wq + g) * PST2 + c * 8 + t * 2];
            uint2 hi = *(const uint2*)&sP[(wq + g + 8) * PST2 + c * 8 + t * 2];
            pa[0] = lo.x; pa[2] = lo.y;
            pa[1] = hi.x; pa[3] = hi.y;
#pragma unroll
            for (int nt = 0; nt < 8; nt++) {
                unsigned bf[2];                       // pre-rounded tf32
                bf[0] = sVst[(c * 8 + t) * KVST + nt * 8 + g];
                bf[1] = sVst[(c * 8 + t + 4) * KVST + nt * 8 + g];
                mma_tf32(o[nt], pa, bf);
            }
        }
    }

    // ---- normalize + store, tf32-rounded (consumed as tf32 by out-proj) ----
    float inv0 = 1.f / l0, inv1 = 1.f / l1;
    float* op = g_ctx + (size_t)(b * S_ + q0 + wq) * 512 + h * 64;
#pragma unroll
    for (int nt = 0; nt < 8; nt++) {
        int col = nt * 8 + t * 2;
        *(float2*)(op + (size_t)g * 512 + col) =
            make_float2(tf32f(o[nt][0] * inv0), tf32f(o[nt][1] * inv0));
        *(float2*)(op + (size_t)(g + 8) * 512 + col) =
            make_float2(tf32f(o[nt][2] * inv1), tf32f(o[nt][3] * inv1));
    }
}

#define ATTN_SMEM ((4 * KVSZ + 64 * PST2) * 4)   // 38912 + 10240 = 49152 B

// ---------------------------------------------------------------------------
// Launch.  inputs: 0 Q,1 K,2 V,3 mask(all-true),4 Wq,5 bq,6 Wk,7 bk,
//                  8 Wv,9 bv,10 Wo,11 bo
// ---------------------------------------------------------------------------
extern "C" void kernel_launch(void* const* d_in, const int* in_sizes, int n_in,
                              void* d_out, int out_size)
{
    const float* Q  = (const float*)d_in[0];
    const float* K  = (const float*)d_in[1];
    const float* V  = (const float*)d_in[2];
    const float* Wq = (const float*)d_in[4];
    const float* bq = (const float*)d_in[5];
    const float* Wk = (const float*)d_in[6];
    const float* bk = (const float*)d_in[7];
    const float* Wv = (const float*)d_in[8];
    const float* bv = (const float*)d_in[9];
    const float* Wo = (const float*)d_in[10];
    const float* bo = (const float*)d_in[11];
    float* out = (float*)d_out;

    cudaFuncSetAttribute(attn_tf32_kernel,
                         cudaFuncAttributeMaxDynamicSharedMemorySize, ATTN_SMEM);
    cudaFuncSetAttribute(gemm_tf32_kernel<true>,
                         cudaFuncAttributeMaxDynamicSharedMemorySize, GEMM_SMEM);
    cudaFuncSetAttribute(gemm_tf32_kernel<false>,
                         cudaFuncAttributeMaxDynamicSharedMemorySize, GEMM_SMEM);

    // Round weights to tf32 once per launch
    prep_weights_kernel<<<(H_ * D_ * HD_) / 256, 256>>>(Wq, Wk, Wv, Wo);

    // QKV projections in one launch (z selects Q/K/V)
    dim3 gq(M_ / GBM, NW_ / GBN, 3);   // 64 x 4 x 3
    gemm_tf32_kernel<true><<<gq, 256, GEMM_SMEM>>>(Q, K, V, bq, bk, bv, nullptr);

    // Causal attention
    dim3 ga(S_ / 64, B_ * H_);         // 32 x 32
    attn_tf32_kernel<<<ga, 128, ATTN_SMEM>>>();

    // Output projection
    dim3 gg(M_ / GBM, NW_ / GBN);      // 64 x 4
    gemm_tf32_kernel<false><<<gg, 256, GEMM_SMEM>>>(nullptr, nullptr, nullptr,
                                                    bo, nullptr, nullptr, out);
}

// round 11
// speedup vs baseline: 1.4634x; 1.1224x over previous
#include <cuda_runtime.h>
#include <cstdint>

// Problem constants
#define B_  4
#define S_  2048
#define D_  512
#define H_  8
#define HD_ 64
#define M_  (B_*S_)       // 8192
#define NW_ 512

// Scratch (device globals)
__device__ float g_q[M_ * NW_];
__device__ float g_k[M_ * NW_];   // head-dim cols pair-permuted: sigma(k)=(k&3)*2+(k>>2)
__device__ float g_v[M_ * NW_];
__device__ float g_ctx[M_ * NW_];
// tf32-rounded weight copies
__device__ float g_wq2[H_ * D_ * HD_];
__device__ float g_wk2[H_ * D_ * HD_];
__device__ float g_wv2[H_ * D_ * HD_];
__device__ float g_wo2[D_ * NW_];

__device__ __forceinline__ unsigned f2tf(float f) {
    unsigned u;
    asm("cvt.rna.tf32.f32 %0, %1;" : "=r"(u) : "f"(f));
    return u;
}
__device__ __forceinline__ float tf32f(float f) {
    return __uint_as_float(f2tf(f));
}
__device__ __forceinline__ float ex2f(float x) {
    float y;
    asm("ex2.approx.ftz.f32 %0, %1;" : "=f"(y) : "f"(x));
    return y;
}

__device__ __forceinline__ void mma_tf32(float* c, const unsigned* a, const unsigned* b) {
    asm volatile("mma.sync.aligned.m16n8k8.row.col.f32.tf32.tf32.f32 "
        "{%0,%1,%2,%3}, {%4,%5,%6,%7}, {%8,%9}, {%0,%1,%2,%3};"
        : "+f"(c[0]), "+f"(c[1]), "+f"(c[2]), "+f"(c[3])
        : "r"(a[0]), "r"(a[1]), "r"(a[2]), "r"(a[3]), "r"(b[0]), "r"(b[1]));
}

__device__ __forceinline__ void cpa16(void* sptr, const void* g) {
    unsigned sa = (unsigned)__cvta_generic_to_shared(sptr);
    asm volatile("cp.async.cg.shared.global [%0], [%1], 16;" :: "r"(sa), "l"(g));
}
#define CP_COMMIT() asm volatile("cp.async.commit_group;" ::: "memory")
#define CP_WAIT0()  asm volatile("cp.async.wait_group 0;" ::: "memory")
#define CP_WAIT1()  asm volatile("cp.async.wait_group 1;" ::: "memory")

// ---------------------------------------------------------------------------
// Prep: round the four weight matrices to tf32 once.
// ---------------------------------------------------------------------------
__global__ __launch_bounds__(256)
void prep_weights_kernel(const float* __restrict__ wq,
                         const float* __restrict__ wk,
                         const float* __restrict__ wv,
                         const float* __restrict__ wo)
{
    int i = blockIdx.x * 256 + threadIdx.x;
    g_wq2[i] = tf32f(wq[i]);
    g_wk2[i] = tf32f(wk[i]);
    g_wv2[i] = tf32f(wv[i]);
    g_wo2[i] = tf32f(wo[i]);
}

// ---------------------------------------------------------------------------
// tf32 GEMM, cp.async 3-stage pipeline (wait_group 1).  R10 structure.
// z==1 (K projection): output stored with pair-permuted head-dim columns.
// ---------------------------------------------------------------------------
#define GBM 128
#define GBN 128
#define GBK 16
#define ASTR 20
#define BSTR 136
#define GEMM_SMEM (3 * (GBM * ASTR + GBK * BSTR) * 4)

template<bool QKV>
__global__ __launch_bounds__(256, 2)
void gemm_tf32_kernel(const float* __restrict__ A0,
                      const float* __restrict__ A1,
                      const float* __restrict__ A2,
                      const float* __restrict__ b0p,
                      const float* __restrict__ b1p,
                      const float* __restrict__ b2p,
                      float* __restrict__ Cout)
{
    const float* A; const float* W; const float* bias; float* C;
    if (QKV) {
        int z = blockIdx.z;
        A    = (z == 0) ? A0 : (z == 1) ? A1 : A2;
        W    = (z == 0) ? g_wq2 : (z == 1) ? g_wk2 : g_wv2;
        bias = (z == 0) ? b0p : (z == 1) ? b1p : b2p;
        C    = (z == 0) ? g_q : (z == 1) ? g_k : g_v;
    } else {
        A = g_ctx; W = g_wo2; bias = b0p; C = Cout;
    }

    extern __shared__ __align__(16) float gsm[];
    float* As = gsm;                        // [3][GBM*ASTR]
    float* Bs = gsm + 3 * GBM * ASTR;       // [3][GBK*BSTR]

    const int tid  = threadIdx.x;
    const int lane = tid & 31;
    const int w    = tid >> 5;
    const int g    = lane >> 2;
    const int t    = lane & 3;

    const int bm0 = blockIdx.x * GBM;
    const int bn0 = blockIdx.y * GBN;
    const int wm0 = (w & 1) * 64;
    const int wn0 = (w >> 1) * 32;

    const int aRow = tid >> 1;
    const int aK   = (tid & 1) * 8;
    const int bR   = tid >> 4;
    const int bN   = (tid & 15) * 4;

    float acc[4][4][4];
#pragma unroll
    for (int mt = 0; mt < 4; mt++)
#pragma unroll
        for (int nt = 0; nt < 4; nt++)
#pragma unroll
            for (int i = 0; i < 4; i++) acc[mt][nt][i] = 0.f;

    auto prefetch = [&](int st, int k0) {
        float* as = As + st * GBM * ASTR;
        float* bs = Bs + st * GBK * BSTR;
        const float* ap = A + (size_t)(bm0 + aRow) * 512 + k0 + aK;
        cpa16(as + aRow * ASTR + aK, ap);
        cpa16(as + aRow * ASTR + aK + 4, ap + 4);
#pragma unroll
        for (int j = 0; j < 2; j++) {
            int n = bn0 + bN + j * 64;
            const float* bp;
            if (QKV) bp = W + (size_t)(n >> 6) * (D_ * 64) + (size_t)(k0 + bR) * 64 + (n & 63);
            else     bp = W + (size_t)(k0 + bR) * 512 + n;
            cpa16(bs + bR * BSTR + bN + j * 64, bp);
        }
    };

    prefetch(0, 0);
    CP_COMMIT();
    prefetch(1, GBK);
    CP_COMMIT();

    for (int it = 0; it < 32; it++) {
        const int st = it % 3;
        CP_WAIT1();
        __syncthreads();
        if (it + 2 < 32) prefetch((it + 2) % 3, (it + 2) * GBK);
        CP_COMMIT();

        const float*    Asf = As + st * GBM * ASTR;
        const unsigned* Bsu = (const unsigned*)(Bs + st * GBK * BSTR);

#pragma unroll
        for (int kc = 0; kc < 16; kc += 8) {
            unsigned af[4][4], bf[4][2];
#pragma unroll
            for (int mt = 0; mt < 4; mt++) {
                int r = wm0 + mt * 16 + g;
                const float* ar  = &Asf[r * ASTR + kc + t];
                const float* ar8 = ar + 8 * ASTR;
                if (QKV) {
                    af[mt][0] = f2tf(ar[0]);
                    af[mt][2] = f2tf(ar[4]);
                    af[mt][1] = f2tf(ar8[0]);
                    af[mt][3] = f2tf(ar8[4]);
                } else {
                    af[mt][0] = __float_as_uint(ar[0]);
                    af[mt][2] = __float_as_uint(ar[4]);
                    af[mt][1] = __float_as_uint(ar8[0]);
                    af[mt][3] = __float_as_uint(ar8[4]);
                }
            }
#pragma unroll
            for (int nt = 0; nt < 4; nt++) {
                int cn = wn0 + nt * 8 + g;
                bf[nt][0] = Bsu[(kc + t) * BSTR + cn];
                bf[nt][1] = Bsu[(kc + t + 4) * BSTR + cn];
            }
#pragma unroll
            for (int mt = 0; mt < 4; mt++)
#pragma unroll
                for (int nt = 0; nt < 4; nt++)
                    mma_tf32(acc[mt][nt], af[mt], bf[nt]);
        }
    }

    const bool kperm = QKV && (blockIdx.z == 1);
    const int k0i = t * 2, k1i = t * 2 + 1;
    const int p0 = (k0i & 3) * 2 + (k0i >> 2);   // sigma(2t)
    const int p1 = (k1i & 3) * 2 + (k1i >> 2);   // sigma(2t+1)

#pragma unroll
    for (int mt = 0; mt < 4; mt++) {
        int r = bm0 + wm0 + mt * 16 + g;
#pragma unroll
        for (int nt = 0; nt < 4; nt++) {
            int col = bn0 + wn0 + nt * 8 + t * 2;
            float bb0 = bias[col], bb1 = bias[col + 1];
            float c0 = acc[mt][nt][0] + bb0, c1 = acc[mt][nt][1] + bb1;
            float c2 = acc[mt][nt][2] + bb0, c3 = acc[mt][nt][3] + bb1;
            if (QKV) {
                c0 = tf32f(c0); c1 = tf32f(c1); c2 = tf32f(c2); c3 = tf32f(c3);
            }
            if (kperm) {   // K: pair-permuted head-dim columns
                int base = bn0 + wn0 + nt * 8;
                C[(size_t)r * 512 + base + p0] = c0;
                C[(size_t)r * 512 + base + p1] = c1;
                C[(size_t)(r + 8) * 512 + base + p0] = c2;
                C[(size_t)(r + 8) * 512 + base + p1] = c3;
            } else {
                *(float2*)(C + (size_t)r * 512 + col)       = make_float2(c0, c1);
                *(float2*)(C + (size_t)(r + 8) * 512 + col) = make_float2(c2, c3);
            }
        }
    }
}

// ---------------------------------------------------------------------------
// Flash attention (causal), tf32 mma, cp.async 3-stage KV ring.
// 4 warps, 64 q-rows (16/warp), 32-key tiles, KVST 72.
//   K pre-permuted in GMEM -> S b-frags are LDS.64 (pair banks 4g+t, clean).
//   V frags scalar LDS.32 (banks 8t+g, clean).  sP [64][40] warp-private.
// Base-2 softmax: log2e folded into Q scale, ex2.approx only.
// smem = (3*2*32*72 + 64*40)*4 = 65536 B -> 3 blocks/SM, regs <= 170.
// ---------------------------------------------------------------------------
#define KVST 72
#define KVSZ (32 * KVST)
#define PST2 40

__global__ __launch_bounds__(128, 3)
void attn_tf32_kernel()
{
    extern __shared__ __align__(16) float asmem[];
    float* sK = asmem;                       // [3][KVSZ]
    float* sV = asmem + 3 * KVSZ;            // [3][KVSZ]
    unsigned* sP = (unsigned*)(asmem + 6 * KVSZ);   // [64*40]

    const int tid  = threadIdx.x;
    const int lane = tid & 31;
    const int w    = tid >> 5;
    const int g    = lane >> 2;
    const int t    = lane & 3;

    const int qt  = gridDim.x - 1 - blockIdx.x;  // heavy tiles first
    const int q0  = qt * 64;
    const int b   = blockIdx.y >> 3;
    const int h   = blockIdx.y & 7;
    const int wq  = w * 16;

    const float* kbase = g_k + (size_t)(b * S_) * 512 + h * 64;
    const float* vbase = g_v + (size_t)(b * S_) * 512 + h * 64;

    auto prefetch_kv = [&](int st, int j0) {
        const float* kp = kbase + (size_t)j0 * 512;
        const float* vp = vbase + (size_t)j0 * 512;
        float* dk = sK + st * KVSZ;
        float* dv = sV + st * KVSZ;
#pragma unroll
        for (int i = 0; i < 4; i++) {
            int ch = tid + i * 128;      // 0..511
            int r  = ch >> 4;            // key row 0..31
            int cc = (ch & 15) * 4;      // float col of 16B chunk
            cpa16(dk + r * KVST + cc, kp + (size_t)r * 512 + cc);
            cpa16(dv + r * KVST + cc, vp + (size_t)r * 512 + cc);
        }
    };

    // Q fragments: logical head-dim indices (g_q unpermuted).
    // Scale = 0.125 * log2(e) folded in; tf32-round after the mul.
    const float QS = 0.125f * 1.4426950408889634f;
    unsigned qf[8][4];
    {
        const float* qp = g_q + (size_t)(b * S_ + q0 + wq) * 512 + h * 64;
#pragma unroll
        for (int c = 0; c < 8; c++) {
            qf[c][0] = f2tf(QS * qp[(size_t)g * 512 + c * 8 + t]);
            qf[c][1] = f2tf(QS * qp[(size_t)(g + 8) * 512 + c * 8 + t]);
            qf[c][2] = f2tf(QS * qp[(size_t)g * 512 + c * 8 + t + 4]);
            qf[c][3] = f2tf(QS * qp[(size_t)(g + 8) * 512 + c * 8 + t + 4]);
        }
    }

    float o[8][4];
#pragma unroll
    for (int nt = 0; nt < 8; nt++)
#pragma unroll
        for (int i = 0; i < 4; i++) o[nt][i] = 0.f;
    float m0 = -1e30f, m1 = -1e30f, l0 = 0.f, l1 = 0.f;

    const int p0slot = (t & 1) * 4 + (t >> 1);
    const int ntiles = (q0 + 64) >> 5;

    prefetch_kv(0, 0);
    CP_COMMIT();
    prefetch_kv(1, 32);
    CP_COMMIT();

    for (int it = 0; it < ntiles; it++) {
        const int st = it % 3;
        const int j0 = it * 32;
        CP_WAIT1();                 // stages it, it+1 landed
        __syncthreads();            // all warps done with stage (it-1)%3
        if (it + 2 < ntiles) prefetch_kv((it + 2) % 3, (it + 2) * 32);
        CP_COMMIT();

        if (j0 > q0 + wq + 15) continue;   // tile fully above this warp's rows

        const unsigned* sKst = (const unsigned*)(sK + st * KVSZ);
        const unsigned* sVst = (const unsigned*)(sV + st * KVSZ);

        // ---- S = Q @ K^T (16 rows x 32 keys); K cols pair-permuted ----
        float s[4][4];
#pragma unroll
        for (int nt = 0; nt < 4; nt++)
#pragma unroll
            for (int i = 0; i < 4; i++) s[nt][i] = 0.f;
#pragma unroll
        for (int c = 0; c < 8; c++)
#pragma unroll
            for (int nt = 0; nt < 4; nt++) {
                uint2 kk = *(const uint2*)(sKst + (nt * 8 + g) * KVST + c * 8 + t * 2);
                unsigned bf[2] = { kk.x, kk.y };   // logical d = c*8+t, c*8+t+4
                mma_tf32(s[nt], qf[c], bf);
            }

        // ---- causal mask (diagonal-overlapping tiles only) ----
        if (j0 + 31 > q0 + wq) {
            int r0 = q0 + wq + g;
#pragma unroll
            for (int nt = 0; nt < 4; nt++) {
                int c0 = j0 + nt * 8 + t * 2;
                if (c0     > r0)     s[nt][0] = -1e30f;
                if (c0 + 1 > r0)     s[nt][1] = -1e30f;
                if (c0     > r0 + 8) s[nt][2] = -1e30f;
                if (c0 + 1 > r0 + 8) s[nt][3] = -1e30f;
            }
        }

        // ---- online softmax (base 2) ----
        float mx0 = -1e30f, mx1 = -1e30f;
#pragma unroll
        for (int nt = 0; nt < 4; nt++) {
            mx0 = fmaxf(mx0, fmaxf(s[nt][0], s[nt][1]));
            mx1 = fmaxf(mx1, fmaxf(s[nt][2], s[nt][3]));
        }
        mx0 = fmaxf(mx0, __shfl_xor_sync(0xffffffffu, mx0, 1));
        mx0 = fmaxf(mx0, __shfl_xor_sync(0xffffffffu, mx0, 2));
        mx1 = fmaxf(mx1, __shfl_xor_sync(0xffffffffu, mx1, 1));
        mx1 = fmaxf(mx1, __shfl_xor_sync(0xffffffffu, mx1, 2));
        float nm0 = fmaxf(m0, mx0), nm1 = fmaxf(m1, mx1);
        float cor0 = ex2f(m0 - nm0), cor1 = ex2f(m1 - nm1);
        m0 = nm0; m1 = nm1;

        float ls0 = 0.f, ls1 = 0.f;
        {
            int rowA = (wq + g) * PST2;
            int rowB = rowA + 8 * PST2;
#pragma unroll
            for (int nt = 0; nt < 4; nt++) {
                float e0 = ex2f(s[nt][0] - nm0);
                float e1 = ex2f(s[nt][1] - nm0);
                float e2 = ex2f(s[nt][2] - nm1);
                float e3 = ex2f(s[nt][3] - nm1);
                ls0 += e0 + e1; ls1 += e2 + e3;
                sP[rowA + nt * 8 + p0slot]     = f2tf(e0);
                sP[rowA + nt * 8 + p0slot + 2] = f2tf(e1);
                sP[rowB + nt * 8 + p0slot]     = f2tf(e2);
                sP[rowB + nt * 8 + p0slot + 2] = f2tf(e3);
            }
        }
        ls0 += __shfl_xor_sync(0xffffffffu, ls0, 1);
        ls0 += __shfl_xor_sync(0xffffffffu, ls0, 2);
        ls1 += __shfl_xor_sync(0xffffffffu, ls1, 1);
        ls1 += __shfl_xor_sync(0xffffffffu, ls1, 2);
        l0 = l0 * cor0 + ls0;
        l1 = l1 * cor1 + ls1;

#pragma unroll
        for (int nt = 0; nt < 8; nt++) {
            o[nt][0] *= cor0; o[nt][1] *= cor0;
            o[nt][2] *= cor1; o[nt][3] *= cor1;
        }
        __syncwarp();   // P visible across this warp (rows are warp-private)

        // ---- O += P @ V ----
#pragma unroll
        for (int c = 0; c < 4; c++) {
            unsigned pa[4];
            uint2 lo = *(const uint2*)&sP[(wq + g) * PST2 + c * 8 + t * 2];
            uint2 hi = *(const uint2*)&sP[(wq + g + 8) * PST2 + c * 8 + t * 2];
            pa[0] = lo.x; pa[2] = lo.y;
            pa[1] = hi.x; pa[3] = hi.y;
#pragma unroll
            for (int nt = 0; nt < 8; nt++) {
                unsigned bf[2];
                bf[0] = sVst[(c * 8 + t) * KVST + nt * 8 + g];
                bf[1] = sVst[(c * 8 + t + 4) * KVST + nt * 8 + g];
                mma_tf32(o[nt], pa, bf);
            }
        }
    }

    // ---- normalize + store, tf32-rounded (consumed as tf32 by out-proj) ----
    float inv0 = 1.f / l0, inv1 = 1.f / l1;
    float* op = g_ctx + (size_t)(b * S_ + q0 + wq) * 512 + h * 64;
#pragma unroll
    for (int nt = 0; nt < 8; nt++) {
        int col = nt * 8 + t * 2;
        *(float2*)(op + (size_t)g * 512 + col) =
            make_float2(tf32f(o[nt][0] * inv0), tf32f(o[nt][1] * inv0));
        *(float2*)(op + (size_t)(g + 8) * 512 + col) =
            make_float2(tf32f(o[nt][2] * inv1), tf32f(o[nt][3] * inv1));
    }
}

#define ATTN_SMEM ((6 * KVSZ + 64 * PST2) * 4)   // 65536 B

// ---------------------------------------------------------------------------
// Launch.  inputs: 0 Q,1 K,2 V,3 mask(all-true),4 Wq,5 bq,6 Wk,7 bk,
//                  8 Wv,9 bv,10 Wo,11 bo
// ---------------------------------------------------------------------------
extern "C" void kernel_launch(void* const* d_in, const int* in_sizes, int n_in,
                              void* d_out, int out_size)
{
    const float* Q  = (const float*)d_in[0];
    const float* K  = (const float*)d_in[1];
    const float* V  = (const float*)d_in[2];
    const float* Wq = (const float*)d_in[4];
    const float* bq = (const float*)d_in[5];
    const float* Wk = (const float*)d_in[6];
    const float* bk = (const float*)d_in[7];
    const float* Wv = (const float*)d_in[8];
    const float* bv = (const float*)d_in[9];
    const float* Wo = (const float*)d_in[10];
    const float* bo = (const float*)d_in[11];
    float* out = (float*)d_out;

    cudaFuncSetAttribute(attn_tf32_kernel,
                         cudaFuncAttributeMaxDynamicSharedMemorySize, ATTN_SMEM);
    cudaFuncSetAttribute(gemm_tf32_kernel<true>,
                         cudaFuncAttributeMaxDynamicSharedMemorySize, GEMM_SMEM);
    cudaFuncSetAttribute(gemm_tf32_kernel<false>,
                         cudaFuncAttributeMaxDynamicSharedMemorySize, GEMM_SMEM);

    // Round weights to tf32 once per launch
    prep_weights_kernel<<<(H_ * D_ * HD_) / 256, 256>>>(Wq, Wk, Wv, Wo);

    // QKV projections in one launch (z selects Q/K/V; z==1 stores K permuted)
    dim3 gq(M_ / GBM, NW_ / GBN, 3);   // 64 x 4 x 3
    gemm_tf32_kernel<true><<<gq, 256, GEMM_SMEM>>>(Q, K, V, bq, bk, bv, nullptr);

    // Causal attention
    dim3 ga(S_ / 64, B_ * H_);         // 32 x 32
    attn_tf32_kernel<<<ga, 128, ATTN_SMEM>>>();

    // Output projection
    dim3 gg(M_ / GBM, NW_ / GBN);      // 64 x 4
    gemm_tf32_kernel<false><<<gg, 256, GEMM_SMEM>>>(nullptr, nullptr, nullptr,
                                                    bo, nullptr, nullptr, out);
}